// round 10
// baseline (speedup 1.0000x reference)
#include <cuda_runtime.h>
#include <cuda_bf16.h>
#include <math.h>
#include <stdint.h>

// ---------------------------------------------------------------------------
// Problem constants
// ---------------------------------------------------------------------------
#define N0 100000
#define N1 50000
#define EMAX 200000
#define HID 128
#define NH 4
#define HD 32
#define NL 2

#define LD0 384   // type0: Q | K_r0 | V_r0
#define LD1 640   // type1: Q | K_r1 | V_r1 | K_r2 | V_r2

// aggr layout: r0 (N1 rows) @0, r1 (N0 rows) @N1*HID, r2 (N1 rows) @(N1+N0)*HID
// ssum lives directly after aggr so one memset clears both.
#define AGGR_FLOATS ((size_t)(N0 + 2 * N1) * HID)
#define SSUM_FLOATS ((size_t)3 * N0 * NH)

// ---------------------------------------------------------------------------
// Static device scratch
// ---------------------------------------------------------------------------
__device__ float g_qkv0[(size_t)N0 * LD0];
__device__ float g_qkv1[(size_t)N1 * LD1];
__device__ float g_aggr[AGGR_FLOATS + SSUM_FLOATS];
__device__ float g_wcat0[HID * LD0];
__device__ float g_wcat1[HID * LD1];
__device__ float g_bcat0[LD0];
__device__ float g_bcat1[LD1];
__device__ float g_win[2 * HID * HID];
__device__ float g_wa[2 * HID * HID];

// ---------------------------------------------------------------------------
// Helpers
// ---------------------------------------------------------------------------
__device__ __forceinline__ float gelu_exact(float x) {
    return 0.5f * x * (1.0f + erff(x * 0.7071067811865476f));
}
__device__ __forceinline__ unsigned f2tf32(float f) {
    unsigned u;
    asm("cvt.rna.tf32.f32 %0, %1;" : "=r"(u) : "f"(f));
    return u;
}
__device__ __forceinline__ void mma_tf32(float* c, const unsigned* a, const unsigned* b) {
    asm("mma.sync.aligned.m16n8k8.row.col.f32.tf32.tf32.f32 "
        "{%0,%1,%2,%3}, {%4,%5,%6,%7}, {%8,%9}, {%0,%1,%2,%3};"
        : "+f"(c[0]), "+f"(c[1]), "+f"(c[2]), "+f"(c[3])
        : "r"(a[0]), "r"(a[1]), "r"(a[2]), "r"(a[3]), "r"(b[0]), "r"(b[1]));
}
__device__ __forceinline__ void cpa16(float* dst, const float* src) {
    unsigned d = (unsigned)__cvta_generic_to_shared(dst);
    asm volatile("cp.async.cg.shared.global [%0], [%1], 16;" :: "r"(d), "l"(src));
}
__device__ __forceinline__ void cp_commit() { asm volatile("cp.async.commit_group;"); }
template <int N>
__device__ __forceinline__ void cp_wait() {
    asm volatile("cp.async.wait_group %0;" :: "n"(N));
}

// ---------------------------------------------------------------------------
// TF32 TC GEMM: cp.async 3-stage, 128x128x16 tiles, 512 threads (16 warps).
//   EPI : 0 none, 1 relu, 2 skip-blend with hprev
//   CVT_A: round A fragments to tf32 at load
//   AGGM: 0 A via cp.async; 1 A = gelu(aggr1/ssum1) (type-0 out-proj);
//         2 A = gelu(aggr1/ssum1 + aggr2/ssum2) (type-1 out-proj)
// ---------------------------------------------------------------------------
#define GBM 128
#define GBN 128
#define AS_LD 20
#define BS_LD 136
#define A_STG (128 * AS_LD)
#define B_STG (16 * BS_LD)
#define GEMM_SMEM (3 * (A_STG + B_STG) * 4)

template <int EPI, int CVT_A, int AGGM>
__global__ __launch_bounds__(512, 2) void gemm_tc(
    const float* __restrict__ A, int lda,
    const float* __restrict__ B, int ldb,
    const float* __restrict__ bias,
    float* __restrict__ C, int ldc, int M,
    const float* __restrict__ hprev, int ldh,
    const float* __restrict__ skipPtr,
    const float* __restrict__ X1, const float* __restrict__ S1,
    const float* __restrict__ X2, const float* __restrict__ S2)
{
    extern __shared__ float smemf[];
    float* AsBase = smemf;
    float* BsBase = smemf + 3 * A_STG;

    const int tid  = threadIdx.x;
    const int wid  = tid >> 5;
    const int lane = tid & 31;
    const int row0 = blockIdx.x * GBM;
    const int col0 = blockIdx.y * GBN;
    const int wm0  = (wid >> 2) * 32;
    const int wn0  = (wid & 3) * 32;
    const int g    = lane >> 2;
    const int tig  = lane & 3;

    const int rA = tid >> 2, kcA = (tid & 3) << 2;
    const int kB = tid >> 5, ncB = (tid & 31) << 2;
    int gArow = row0 + rA; if (gArow >= M) gArow = M - 1;
    const float* gA = A + (size_t)gArow * lda + kcA;
    const float* gB = B + (size_t)kB * ldb + col0 + ncB;

    auto stage_load = [&](int s, int k0) {
        if (AGGM == 0) {
            cpa16(AsBase + s * A_STG + rA * AS_LD + kcA, gA + k0);
        } else {
            int h = (k0 + kcA) >> 5;
            float inv1 = 1.f / (S1[(size_t)gArow * NH + h] + 1e-16f);
            float4 v1 = *reinterpret_cast<const float4*>(
                X1 + (size_t)gArow * HID + k0 + kcA);
            float4 o = make_float4(v1.x * inv1, v1.y * inv1,
                                   v1.z * inv1, v1.w * inv1);
            if (AGGM == 2) {
                float inv2 = 1.f / (S2[(size_t)gArow * NH + h] + 1e-16f);
                float4 v2 = *reinterpret_cast<const float4*>(
                    X2 + (size_t)gArow * HID + k0 + kcA);
                o.x += v2.x * inv2; o.y += v2.y * inv2;
                o.z += v2.z * inv2; o.w += v2.w * inv2;
            }
            o.x = __uint_as_float(f2tf32(gelu_exact(o.x)));
            o.y = __uint_as_float(f2tf32(gelu_exact(o.y)));
            o.z = __uint_as_float(f2tf32(gelu_exact(o.z)));
            o.w = __uint_as_float(f2tf32(gelu_exact(o.w)));
            *reinterpret_cast<float4*>(AsBase + s * A_STG + rA * AS_LD + kcA) = o;
        }
        cpa16(BsBase + s * B_STG + kB * BS_LD + ncB, gB + (size_t)k0 * ldb);
    };

    stage_load(0, 0);  cp_commit();
    stage_load(1, 16); cp_commit();

    float acc[2][4][4];
#pragma unroll
    for (int i = 0; i < 2; i++)
#pragma unroll
        for (int j = 0; j < 4; j++)
#pragma unroll
            for (int q = 0; q < 4; q++) acc[i][j][q] = 0.f;

#pragma unroll
    for (int kt = 0; kt < 8; kt++) {
        cp_wait<1>();
        __syncthreads();
        if (kt + 2 < 8) stage_load((kt + 2) % 3, (kt + 2) * 16);
        cp_commit();

        const float* Ast = AsBase + (kt % 3) * A_STG;
        const float* Bst = BsBase + (kt % 3) * B_STG;
#pragma unroll
        for (int k8 = 0; k8 < 2; k8++) {
            const int kk = k8 * 8;
            unsigned aR[2][4], bR[4][2];
#pragma unroll
            for (int mt = 0; mt < 2; mt++) {
                int m = wm0 + mt * 16 + g;
                float a0 = Ast[(size_t)m * AS_LD + kk + tig];
                float a1 = Ast[(size_t)(m + 8) * AS_LD + kk + tig];
                float a2 = Ast[(size_t)m * AS_LD + kk + tig + 4];
                float a3 = Ast[(size_t)(m + 8) * AS_LD + kk + tig + 4];
                if (CVT_A) {
                    aR[mt][0] = f2tf32(a0); aR[mt][1] = f2tf32(a1);
                    aR[mt][2] = f2tf32(a2); aR[mt][3] = f2tf32(a3);
                } else {
                    aR[mt][0] = __float_as_uint(a0); aR[mt][1] = __float_as_uint(a1);
                    aR[mt][2] = __float_as_uint(a2); aR[mt][3] = __float_as_uint(a3);
                }
            }
#pragma unroll
            for (int nt = 0; nt < 4; nt++) {
                int n = wn0 + nt * 8 + g;
                bR[nt][0] = __float_as_uint(Bst[(size_t)(kk + tig) * BS_LD + n]);
                bR[nt][1] = __float_as_uint(Bst[(size_t)(kk + tig + 4) * BS_LD + n]);
            }
#pragma unroll
            for (int mt = 0; mt < 2; mt++)
#pragma unroll
                for (int nt = 0; nt < 4; nt++)
                    mma_tf32(acc[mt][nt], aR[mt], bR[nt]);
        }
    }

    float sgate = 0.f;
    if (EPI == 2) sgate = 1.f / (1.f + expf(-(*skipPtr)));

#pragma unroll
    for (int mt = 0; mt < 2; mt++) {
#pragma unroll
        for (int rr = 0; rr < 2; rr++) {
            int grow = row0 + wm0 + mt * 16 + g + rr * 8;
            if (grow >= M) continue;
#pragma unroll
            for (int nt = 0; nt < 4; nt++) {
                int col = col0 + wn0 + nt * 8 + 2 * tig;
                float v0 = acc[mt][nt][rr * 2 + 0] + bias[col];
                float v1 = acc[mt][nt][rr * 2 + 1] + bias[col + 1];
                if (EPI == 1) { v0 = fmaxf(v0, 0.f); v1 = fmaxf(v1, 0.f); }
                if (EPI == 2) {
                    const float* hp = hprev + (size_t)grow * ldh + col;
                    v0 = sgate * v0 + (1.f - sgate) * hp[0];
                    v1 = sgate * v1 + (1.f - sgate) * hp[1];
                }
                *reinterpret_cast<float2*>(C + (size_t)grow * ldc + col) =
                    make_float2(v0, v1);
            }
        }
    }
}

// ---------------------------------------------------------------------------
// Weight prep (all outputs tf32-rounded). A==nullptr -> copy.
// ---------------------------------------------------------------------------
struct WPrepSec {
    const float* W; const float* b; const float* A;
    float* Wd; float* bd; int ld;
};
struct WPrepN { WPrepSec s[10]; };

__global__ void prep_w_k(WPrepN P)
{
    WPrepSec p = P.s[blockIdx.y];
    int col = threadIdx.x;
    int i = blockIdx.x;
    if (p.A == nullptr) {
        if (i < HID)
            p.Wd[(size_t)i * p.ld + col] =
                __uint_as_float(f2tf32(p.W[(size_t)i * HID + col]));
        else if (p.bd) p.bd[col] = p.b[col];
        return;
    }
    int h = col >> 5, e = col & 31;
    const float* Ah = p.A + h * HD * HD;
    if (i < HID) {
        const float* wrow = p.W + (size_t)i * HID + h * HD;
        float acc = 0.f;
#pragma unroll
        for (int d = 0; d < HD; d++) acc = fmaf(wrow[d], Ah[d * HD + e], acc);
        p.Wd[(size_t)i * p.ld + col] = __uint_as_float(f2tf32(acc));
    } else if (p.bd) {
        const float* brow = p.b + h * HD;
        float acc = 0.f;
#pragma unroll
        for (int d = 0; d < HD; d++) acc = fmaf(brow[d], Ah[d * HD + e], acc);
        p.bd[col] = acc;
    }
}

// ---------------------------------------------------------------------------
// Single-pass fused edge kernel (warp per edge, all 3 relations per launch)
// ---------------------------------------------------------------------------
struct EdgeRel {
    const int* src; const int* dst;
    const float* q; int ldq;
    const float* kr; int ldk;
    const float* vr; int ldv;
    const float* prel;
    float* ssum; float* aggr;
};
struct Edge3 { EdgeRel r[3]; int off1, off2, total; };

__global__ void edge_fused_k(Edge3 P)
{
    int w = blockIdx.x * (blockDim.x >> 5) + (threadIdx.x >> 5);
    if (w >= P.total) return;
    int lane = threadIdx.x & 31;
    int ri = (w >= P.off1) + (w >= P.off2);
    int base = ri == 0 ? 0 : (ri == 1 ? P.off1 : P.off2);
    EdgeRel R = P.r[ri];
    int e = w - base;
    int s = __ldg(&R.src[e]), d = __ldg(&R.dst[e]);
    float4 qv = *reinterpret_cast<const float4*>(R.q + (size_t)d * R.ldq + lane * 4);
    float4 kv = *reinterpret_cast<const float4*>(R.kr + (size_t)s * R.ldk + lane * 4);
    float acc = qv.x * kv.x + qv.y * kv.y + qv.z * kv.z + qv.w * kv.w;
    acc += __shfl_xor_sync(0xffffffffu, acc, 1);
    acc += __shfl_xor_sync(0xffffffffu, acc, 2);
    acc += __shfl_xor_sync(0xffffffffu, acc, 4);
    int h = lane >> 3;
    float a = acc * __ldg(&R.prel[h]) * 0.17677669529663689f; // 1/sqrt(32)
    float ex = expf(a);
    float4 v = *reinterpret_cast<const float4*>(R.vr + (size_t)s * R.ldv + lane * 4);
    float* p = R.aggr + (size_t)d * HID + lane * 4;
    asm volatile("red.global.add.v4.f32 [%0], {%1,%2,%3,%4};"
                 :: "l"(p), "f"(v.x * ex), "f"(v.y * ex),
                    "f"(v.z * ex), "f"(v.w * ex)
                 : "memory");
    if ((lane & 7) == 0)
        atomicAdd(&R.ssum[(size_t)d * NH + h], ex);
}

// ---------------------------------------------------------------------------
// Host orchestration
// ---------------------------------------------------------------------------
extern "C" void kernel_launch(void* const* d_in, const int* in_sizes, int n_in,
                              void* d_out, int out_size)
{
    const float* x0   = (const float*)d_in[0];
    const float* x1   = (const float*)d_in[1];
    const int* srcp[3] = {(const int*)d_in[2], (const int*)d_in[4], (const int*)d_in[6]};
    const int* dstp[3] = {(const int*)d_in[3], (const int*)d_in[5], (const int*)d_in[7]};
    const int  Ecnt[3] = {in_sizes[2], in_sizes[4], in_sizes[6]};
    const float* W_in = (const float*)d_in[8];
    const float* b_in = (const float*)d_in[9];
    const float* Wk   = (const float*)d_in[10];
    const float* bk   = (const float*)d_in[11];
    const float* Wq   = (const float*)d_in[12];
    const float* bq   = (const float*)d_in[13];
    const float* Wv   = (const float*)d_in[14];
    const float* bv   = (const float*)d_in[15];
    const float* Wa   = (const float*)d_in[16];
    const float* ba   = (const float*)d_in[17];
    const float* skip = (const float*)d_in[18];
    const float* a_rel = (const float*)d_in[19];
    const float* m_rel = (const float*)d_in[20];
    const float* p_rel = (const float*)d_in[21];

    float* out = (float*)d_out;
    const int OW = HID * (NL + 1);       // 384
    float* y0 = out;
    float* y1 = out + (size_t)N0 * OW;

    float *qkv0, *qkv1, *aggr, *wcat0, *wcat1, *bcat0, *bcat1, *win, *wa;
    cudaGetSymbolAddress((void**)&qkv0,  g_qkv0);
    cudaGetSymbolAddress((void**)&qkv1,  g_qkv1);
    cudaGetSymbolAddress((void**)&aggr,  g_aggr);
    cudaGetSymbolAddress((void**)&wcat0, g_wcat0);
    cudaGetSymbolAddress((void**)&wcat1, g_wcat1);
    cudaGetSymbolAddress((void**)&bcat0, g_bcat0);
    cudaGetSymbolAddress((void**)&bcat1, g_bcat1);
    cudaGetSymbolAddress((void**)&win,   g_win);
    cudaGetSymbolAddress((void**)&wa,    g_wa);
    float* ssum = aggr + AGGR_FLOATS;

    cudaFuncSetAttribute(gemm_tc<0,1,0>, cudaFuncAttributeMaxDynamicSharedMemorySize, GEMM_SMEM);
    cudaFuncSetAttribute(gemm_tc<1,1,0>, cudaFuncAttributeMaxDynamicSharedMemorySize, GEMM_SMEM);
    cudaFuncSetAttribute(gemm_tc<2,0,1>, cudaFuncAttributeMaxDynamicSharedMemorySize, GEMM_SMEM);
    cudaFuncSetAttribute(gemm_tc<2,0,2>, cudaFuncAttributeMaxDynamicSharedMemorySize, GEMM_SMEM);

    const dim3 g0((N0 + GBM - 1) / GBM);
    const dim3 g1((N1 + GBM - 1) / GBM);

    // ---- W_in rounding copies, then input projection
    {
        WPrepN P0;
        P0.s[0] = {W_in,             b_in, nullptr, win,             nullptr, HID};
        P0.s[1] = {W_in + HID * HID, b_in, nullptr, win + HID * HID, nullptr, HID};
        prep_w_k<<<dim3(HID + 1, 2), HID>>>(P0);
    }
    gemm_tc<1,1,0><<<g0, 512, GEMM_SMEM>>>(x0, HID, win, HID, b_in, y0, OW, N0,
                                           nullptr, 0, nullptr,
                                           nullptr, nullptr, nullptr, nullptr);
    gemm_tc<1,1,0><<<g1, 512, GEMM_SMEM>>>(x1, HID, win + HID * HID, HID, b_in + HID,
                                           y1, OW, N1, nullptr, 0, nullptr,
                                           nullptr, nullptr, nullptr, nullptr);

    for (int l = 0; l < NL; l++) {
        const float* h0 = y0 + l * HID;  // lda = OW
        const float* h1 = y1 + l * HID;

        // ---- fused weight prep
        WPrepN P;
        const float* WkL0 = Wk + (size_t)(l * 2 + 0) * HID * HID;
        const float* WkL1 = Wk + (size_t)(l * 2 + 1) * HID * HID;
        const float* WvL0 = Wv + (size_t)(l * 2 + 0) * HID * HID;
        const float* WvL1 = Wv + (size_t)(l * 2 + 1) * HID * HID;
        const float* ar0 = a_rel + (size_t)(l * 3 + 0) * NH * HD * HD;
        const float* ar1 = a_rel + (size_t)(l * 3 + 1) * NH * HD * HD;
        const float* ar2 = a_rel + (size_t)(l * 3 + 2) * NH * HD * HD;
        const float* mr0 = m_rel + (size_t)(l * 3 + 0) * NH * HD * HD;
        const float* mr1 = m_rel + (size_t)(l * 3 + 1) * NH * HD * HD;
        const float* mr2 = m_rel + (size_t)(l * 3 + 2) * NH * HD * HD;
        P.s[0] = {Wq + (size_t)(l*2+0)*HID*HID, bq + (l*2+0)*HID, nullptr, wcat0,       bcat0,       LD0};
        P.s[1] = {WkL0, bk + (l*2+0)*HID, ar0, wcat0 + 128, bcat0 + 128, LD0};
        P.s[2] = {WvL0, bv + (l*2+0)*HID, mr0, wcat0 + 256, bcat0 + 256, LD0};
        P.s[3] = {Wq + (size_t)(l*2+1)*HID*HID, bq + (l*2+1)*HID, nullptr, wcat1,       bcat1,       LD1};
        P.s[4] = {WkL1, bk + (l*2+1)*HID, ar1, wcat1 + 128, bcat1 + 128, LD1};
        P.s[5] = {WvL1, bv + (l*2+1)*HID, mr1, wcat1 + 256, bcat1 + 256, LD1};
        P.s[6] = {WkL1, bk + (l*2+1)*HID, ar2, wcat1 + 384, bcat1 + 384, LD1};
        P.s[7] = {WvL1, bv + (l*2+1)*HID, mr2, wcat1 + 512, bcat1 + 512, LD1};
        P.s[8] = {Wa + (size_t)(l*2+0)*HID*HID, nullptr, nullptr, wa,             nullptr, HID};
        P.s[9] = {Wa + (size_t)(l*2+1)*HID*HID, nullptr, nullptr, wa + HID * HID, nullptr, HID};
        prep_w_k<<<dim3(HID + 1, 10), HID>>>(P);

        // ---- fused projections
        gemm_tc<0,1,0><<<dim3(g0.x, LD0 / GBN), 512, GEMM_SMEM>>>(
            h0, OW, wcat0, LD0, bcat0, qkv0, LD0, N0, nullptr, 0, nullptr,
            nullptr, nullptr, nullptr, nullptr);
        gemm_tc<0,1,0><<<dim3(g1.x, LD1 / GBN), 512, GEMM_SMEM>>>(
            h1, OW, wcat1, LD1, bcat1, qkv1, LD1, N1, nullptr, 0, nullptr,
            nullptr, nullptr, nullptr, nullptr);

        // one memset covers aggr + ssum (contiguous)
        cudaMemsetAsync(aggr, 0, (AGGR_FLOATS + SSUM_FLOATS) * sizeof(float), 0);

        // ---- single-pass fused edge stage
        Edge3 EP;
        const float* qd_tab[3]  = {qkv1,        qkv0,        qkv1};
        const int    ldq_tab[3] = {LD1,         LD0,         LD1};
        const float* kr_tab[3]  = {qkv0 + 128,  qkv1 + 128,  qkv1 + 384};
        const float* vr_tab[3]  = {qkv0 + 256,  qkv1 + 256,  qkv1 + 512};
        const int    lds_tab[3] = {LD0,         LD1,         LD1};
        float* aggr_tab[3] = {aggr,
                              aggr + (size_t)N1 * HID,
                              aggr + (size_t)(N1 + N0) * HID};
        for (int r = 0; r < 3; r++) {
            EP.r[r].src  = srcp[r];
            EP.r[r].dst  = dstp[r];
            EP.r[r].q    = qd_tab[r];  EP.r[r].ldq = ldq_tab[r];
            EP.r[r].kr   = kr_tab[r];  EP.r[r].ldk = lds_tab[r];
            EP.r[r].vr   = vr_tab[r];  EP.r[r].ldv = lds_tab[r];
            EP.r[r].prel = p_rel + (size_t)(l * 3 + r) * NH;
            EP.r[r].ssum = ssum + (size_t)r * N0 * NH;
            EP.r[r].aggr = aggr_tab[r];
        }
        EP.off1 = Ecnt[0];
        EP.off2 = Ecnt[0] + Ecnt[1];
        EP.total = Ecnt[0] + Ecnt[1] + Ecnt[2];
        int eBlocks = (EP.total + 7) / 8;
        edge_fused_k<<<eBlocks, 256>>>(EP);

        // ---- output projection with fused normalize+combine+gelu A-path
        gemm_tc<2,0,1><<<g0, 512, GEMM_SMEM>>>(
            aggr + (size_t)N1 * HID, HID,          // A ptr (row clamp source)
            wa, HID, ba + (l * 2 + 0) * HID,
            y0 + (l + 1) * HID, OW, N0,
            h0, OW, skip + l * 2 + 0,
            aggr + (size_t)N1 * HID, ssum + (size_t)N0 * NH,   // X1, S1 (r1)
            nullptr, nullptr);
        gemm_tc<2,0,2><<<g1, 512, GEMM_SMEM>>>(
            aggr, HID,
            wa + HID * HID, HID, ba + (l * 2 + 1) * HID,
            y1 + (l + 1) * HID, OW, N1,
            h1, OW, skip + l * 2 + 1,
            aggr, ssum,                                          // X1, S1 (r0)
            aggr + (size_t)(N1 + N0) * HID, ssum + (size_t)2 * N0 * NH); // X2, S2 (r2)
    }
}

// round 11
// speedup vs baseline: 1.2565x; 1.2565x over previous
#include <cuda_runtime.h>
#include <cuda_bf16.h>
#include <math.h>
#include <stdint.h>

// ---------------------------------------------------------------------------
// Problem constants
// ---------------------------------------------------------------------------
#define N0 100000
#define N1 50000
#define EMAX 200000
#define HID 128
#define NH 4
#define HD 32
#define NL 2

#define LD0 384   // type0: Q | K_r0 | V_r0
#define LD1 640   // type1: Q | K_r1 | V_r1 | K_r2 | V_r2

#define NSEG (N1 + N0 + N1)   // deg/rowptr segments: r0(N1) | r1(N0) | r2(N1)

// aggr layout: r0 (N1 rows) @0, r1 (N0 rows) @N1*HID, r2 (N1 rows) @(N1+N0)*HID
// ssum lives directly after aggr so one memset clears both.
#define AGGR_FLOATS ((size_t)(N0 + 2 * N1) * HID)
#define SSUM_FLOATS ((size_t)3 * N0 * NH)

// ---------------------------------------------------------------------------
// Static device scratch
// ---------------------------------------------------------------------------
__device__ float g_qkv0[(size_t)N0 * LD0];
__device__ float g_qkv1[(size_t)N1 * LD1];
__device__ float g_agg[(size_t)(N0 + N1) * HID];
__device__ float g_aggr[AGGR_FLOATS + SSUM_FLOATS];
__device__ int   g_deg[NSEG];
__device__ int   g_rowptr[NSEG + 1];
__device__ int   g_csr_src[3 * EMAX];
__device__ int   g_csr_dst[3 * EMAX];
__device__ float g_wcat0[NL * HID * LD0];
__device__ float g_wcat1[NL * HID * LD1];
__device__ float g_bcat0[NL * LD0];
__device__ float g_bcat1[NL * LD1];
__device__ float g_win[2 * HID * HID];
__device__ float g_wa[NL * 2 * HID * HID];

// ---------------------------------------------------------------------------
// Helpers
// ---------------------------------------------------------------------------
__device__ __forceinline__ float gelu_exact(float x) {
    return 0.5f * x * (1.0f + erff(x * 0.7071067811865476f));
}
__device__ __forceinline__ unsigned f2tf32(float f) {
    unsigned u;
    asm("cvt.rna.tf32.f32 %0, %1;" : "=r"(u) : "f"(f));
    return u;
}
__device__ __forceinline__ void mma_tf32(float* c, const unsigned* a, const unsigned* b) {
    asm("mma.sync.aligned.m16n8k8.row.col.f32.tf32.tf32.f32 "
        "{%0,%1,%2,%3}, {%4,%5,%6,%7}, {%8,%9}, {%0,%1,%2,%3};"
        : "+f"(c[0]), "+f"(c[1]), "+f"(c[2]), "+f"(c[3])
        : "r"(a[0]), "r"(a[1]), "r"(a[2]), "r"(a[3]), "r"(b[0]), "r"(b[1]));
}
__device__ __forceinline__ void cpa16(float* dst, const float* src) {
    unsigned d = (unsigned)__cvta_generic_to_shared(dst);
    asm volatile("cp.async.cg.shared.global [%0], [%1], 16;" :: "r"(d), "l"(src));
}
__device__ __forceinline__ void cp_commit() { asm volatile("cp.async.commit_group;"); }
template <int N>
__device__ __forceinline__ void cp_wait() {
    asm volatile("cp.async.wait_group %0;" :: "n"(N));
}

// ---------------------------------------------------------------------------
// TF32 TC GEMM (R6 champion): cp.async 3-stage, 128x128x16 tiles, 512 threads.
//   EPI: 0 none, 1 relu, 2 skip-blend with hprev   CVT_A: round A at frag load
// ---------------------------------------------------------------------------
#define GBM 128
#define GBN 128
#define AS_LD 20
#define BS_LD 136
#define A_STG (128 * AS_LD)
#define B_STG (16 * BS_LD)
#define GEMM_SMEM (3 * (A_STG + B_STG) * 4)

template <int EPI, int CVT_A>
__global__ __launch_bounds__(512, 2) void gemm_tc(
    const float* __restrict__ A, int lda,
    const float* __restrict__ B, int ldb,
    const float* __restrict__ bias,
    float* __restrict__ C, int ldc, int M,
    const float* __restrict__ hprev, int ldh,
    const float* __restrict__ skipPtr)
{
    extern __shared__ float smemf[];
    float* AsBase = smemf;
    float* BsBase = smemf + 3 * A_STG;

    const int tid  = threadIdx.x;
    const int wid  = tid >> 5;
    const int lane = tid & 31;
    const int row0 = blockIdx.x * GBM;
    const int col0 = blockIdx.y * GBN;
    const int wm0  = (wid >> 2) * 32;
    const int wn0  = (wid & 3) * 32;
    const int g    = lane >> 2;
    const int tig  = lane & 3;

    const int rA = tid >> 2, kcA = (tid & 3) << 2;
    const int kB = tid >> 5, ncB = (tid & 31) << 2;
    int gArow = row0 + rA; if (gArow >= M) gArow = M - 1;
    const float* gA = A + (size_t)gArow * lda + kcA;
    const float* gB = B + (size_t)kB * ldb + col0 + ncB;

    auto stage_load = [&](int s, int k0) {
        cpa16(AsBase + s * A_STG + rA * AS_LD + kcA, gA + k0);
        cpa16(BsBase + s * B_STG + kB * BS_LD + ncB, gB + (size_t)k0 * ldb);
    };

    stage_load(0, 0);  cp_commit();
    stage_load(1, 16); cp_commit();

    float acc[2][4][4];
#pragma unroll
    for (int i = 0; i < 2; i++)
#pragma unroll
        for (int j = 0; j < 4; j++)
#pragma unroll
            for (int q = 0; q < 4; q++) acc[i][j][q] = 0.f;

#pragma unroll
    for (int kt = 0; kt < 8; kt++) {
        cp_wait<1>();
        __syncthreads();
        if (kt + 2 < 8) stage_load((kt + 2) % 3, (kt + 2) * 16);
        cp_commit();

        const float* Ast = AsBase + (kt % 3) * A_STG;
        const float* Bst = BsBase + (kt % 3) * B_STG;
#pragma unroll
        for (int k8 = 0; k8 < 2; k8++) {
            const int kk = k8 * 8;
            unsigned aR[2][4], bR[4][2];
#pragma unroll
            for (int mt = 0; mt < 2; mt++) {
                int m = wm0 + mt * 16 + g;
                float a0 = Ast[(size_t)m * AS_LD + kk + tig];
                float a1 = Ast[(size_t)(m + 8) * AS_LD + kk + tig];
                float a2 = Ast[(size_t)m * AS_LD + kk + tig + 4];
                float a3 = Ast[(size_t)(m + 8) * AS_LD + kk + tig + 4];
                if (CVT_A) {
                    aR[mt][0] = f2tf32(a0); aR[mt][1] = f2tf32(a1);
                    aR[mt][2] = f2tf32(a2); aR[mt][3] = f2tf32(a3);
                } else {
                    aR[mt][0] = __float_as_uint(a0); aR[mt][1] = __float_as_uint(a1);
                    aR[mt][2] = __float_as_uint(a2); aR[mt][3] = __float_as_uint(a3);
                }
            }
#pragma unroll
            for (int nt = 0; nt < 4; nt++) {
                int n = wn0 + nt * 8 + g;
                bR[nt][0] = __float_as_uint(Bst[(size_t)(kk + tig) * BS_LD + n]);
                bR[nt][1] = __float_as_uint(Bst[(size_t)(kk + tig + 4) * BS_LD + n]);
            }
#pragma unroll
            for (int mt = 0; mt < 2; mt++)
#pragma unroll
                for (int nt = 0; nt < 4; nt++)
                    mma_tf32(acc[mt][nt], aR[mt], bR[nt]);
        }
    }

    float sgate = 0.f;
    if (EPI == 2) sgate = 1.f / (1.f + expf(-(*skipPtr)));

#pragma unroll
    for (int mt = 0; mt < 2; mt++) {
#pragma unroll
        for (int rr = 0; rr < 2; rr++) {
            int grow = row0 + wm0 + mt * 16 + g + rr * 8;
            if (grow >= M) continue;
#pragma unroll
            for (int nt = 0; nt < 4; nt++) {
                int col = col0 + wn0 + nt * 8 + 2 * tig;
                float v0 = acc[mt][nt][rr * 2 + 0] + bias[col];
                float v1 = acc[mt][nt][rr * 2 + 1] + bias[col + 1];
                if (EPI == 1) { v0 = fmaxf(v0, 0.f); v1 = fmaxf(v1, 0.f); }
                if (EPI == 2) {
                    const float* hp = hprev + (size_t)grow * ldh + col;
                    v0 = sgate * v0 + (1.f - sgate) * hp[0];
                    v1 = sgate * v1 + (1.f - sgate) * hp[1];
                }
                *reinterpret_cast<float2*>(C + (size_t)grow * ldc + col) =
                    make_float2(v0, v1);
            }
        }
    }
}

// ---------------------------------------------------------------------------
// Weight prep: 22 sections in one launch. A==nullptr -> tf32-rounded copy.
// ---------------------------------------------------------------------------
struct WPrepSec {
    const float* W; const float* b; const float* A;
    float* Wd; float* bd; int ld;
};
struct WPrepN { WPrepSec s[22]; };

__global__ void prep_w_k(WPrepN P)
{
    WPrepSec p = P.s[blockIdx.y];
    int col = threadIdx.x;
    int i = blockIdx.x;
    if (p.A == nullptr) {
        if (i < HID)
            p.Wd[(size_t)i * p.ld + col] =
                __uint_as_float(f2tf32(p.W[(size_t)i * HID + col]));
        else if (p.bd) p.bd[col] = p.b[col];
        return;
    }
    int h = col >> 5, e = col & 31;
    const float* Ah = p.A + h * HD * HD;
    if (i < HID) {
        const float* wrow = p.W + (size_t)i * HID + h * HD;
        float acc = 0.f;
#pragma unroll
        for (int d = 0; d < HD; d++) acc = fmaf(wrow[d], Ah[d * HD + e], acc);
        p.Wd[(size_t)i * p.ld + col] = __uint_as_float(f2tf32(acc));
    } else if (p.bd) {
        const float* brow = p.b + h * HD;
        float acc = 0.f;
#pragma unroll
        for (int d = 0; d < HD; d++) acc = fmaf(brow[d], Ah[d * HD + e], acc);
        p.bd[col] = acc;
    }
}

// ---------------------------------------------------------------------------
// Edge sort (CSR-order edge list): histogram -> scan -> scatter (src AND dst)
// ---------------------------------------------------------------------------
struct CsrP {
    const int* src[3]; const int* dst[3];
    int segbase[3]; int off1, off2, total;
    int* deg; const int* rowptr; int* csr_src; int* csr_dst;
};

__global__ void hist_k(CsrP P)
{
    int i = blockIdx.x * blockDim.x + threadIdx.x;
    if (i >= P.total) return;
    int ri = (i >= P.off1) + (i >= P.off2);
    int e = i - (ri == 0 ? 0 : (ri == 1 ? P.off1 : P.off2));
    int d = __ldg(&P.dst[ri][e]);
    atomicAdd(&P.deg[P.segbase[ri] + d], 1);
}

__global__ void scatter_k(CsrP P)
{
    int i = blockIdx.x * blockDim.x + threadIdx.x;
    if (i >= P.total) return;
    int ri = (i >= P.off1) + (i >= P.off2);
    int e = i - (ri == 0 ? 0 : (ri == 1 ? P.off1 : P.off2));
    int d = __ldg(&P.dst[ri][e]);
    int sb = P.segbase[ri] + d;
    int slot = __ldg(&P.rowptr[sb]) + atomicAdd(&P.deg[sb], 1);
    P.csr_src[slot] = __ldg(&P.src[ri][e]);
    P.csr_dst[slot] = d;
}

// Single-block exclusive scan (1024 threads, 4 elems/thread/chunk)
__global__ void scan_k(const int* __restrict__ deg, int* __restrict__ rowptr, int n)
{
    __shared__ int warpsum[32];
    __shared__ int carrySh;
    const int tid = threadIdx.x, lane = tid & 31, wid = tid >> 5;
    if (tid == 0) { carrySh = 0; rowptr[0] = 0; }
    __syncthreads();
    for (int base = 0; base < n; base += 4096) {
        int i0 = base + tid * 4;
        int v[4]; int s = 0;
#pragma unroll
        for (int u = 0; u < 4; u++) { int i = i0 + u; v[u] = (i < n) ? deg[i] : 0; s += v[u]; }
        int ss = s;
#pragma unroll
        for (int off = 1; off < 32; off <<= 1) {
            int t = __shfl_up_sync(0xffffffffu, ss, off);
            if (lane >= off) ss += t;
        }
        if (lane == 31) warpsum[wid] = ss;
        __syncthreads();
        if (wid == 0) {
            int ws = warpsum[lane];
#pragma unroll
            for (int off = 1; off < 32; off <<= 1) {
                int t = __shfl_up_sync(0xffffffffu, ws, off);
                if (lane >= off) ws += t;
            }
            warpsum[lane] = ws;
        }
        __syncthreads();
        int carry = carrySh;
        int wbase = wid ? warpsum[wid - 1] : 0;
        int run = carry + wbase + ss - s;
#pragma unroll
        for (int u = 0; u < 4; u++) {
            int i = i0 + u;
            if (i < n) { run += v[u]; rowptr[i + 1] = run; }
        }
        __syncthreads();
        if (tid == 0) carrySh = carry + warpsum[31];
        __syncthreads();
    }
}

// ---------------------------------------------------------------------------
// Single-pass fused edge kernel (warp per edge; edges pre-sorted by dst)
// ---------------------------------------------------------------------------
struct EdgeRel {
    const int* src; const int* dst;
    const float* q; int ldq;
    const float* kr; int ldk;
    const float* vr; int ldv;
    const float* prel;
    float* ssum; float* aggr;
};
struct Edge3 { EdgeRel r[3]; int off1, off2, total; };

__global__ void edge_fused_k(Edge3 P)
{
    int w = blockIdx.x * (blockDim.x >> 5) + (threadIdx.x >> 5);
    if (w >= P.total) return;
    int lane = threadIdx.x & 31;
    int ri = (w >= P.off1) + (w >= P.off2);
    int base = ri == 0 ? 0 : (ri == 1 ? P.off1 : P.off2);
    EdgeRel R = P.r[ri];
    int e = w - base;
    int s = __ldg(&R.src[e]), d = __ldg(&R.dst[e]);
    float4 qv = *reinterpret_cast<const float4*>(R.q + (size_t)d * R.ldq + lane * 4);
    float4 kv = *reinterpret_cast<const float4*>(R.kr + (size_t)s * R.ldk + lane * 4);
    float acc = qv.x * kv.x + qv.y * kv.y + qv.z * kv.z + qv.w * kv.w;
    acc += __shfl_xor_sync(0xffffffffu, acc, 1);
    acc += __shfl_xor_sync(0xffffffffu, acc, 2);
    acc += __shfl_xor_sync(0xffffffffu, acc, 4);
    int h = lane >> 3;
    float a = acc * __ldg(&R.prel[h]) * 0.17677669529663689f; // 1/sqrt(32)
    float ex = expf(a);
    float4 v = *reinterpret_cast<const float4*>(R.vr + (size_t)s * R.ldv + lane * 4);
    float* p = R.aggr + (size_t)d * HID + lane * 4;
    asm volatile("red.global.add.v4.f32 [%0], {%1,%2,%3,%4};"
                 :: "l"(p), "f"(v.x * ex), "f"(v.y * ex),
                    "f"(v.z * ex), "f"(v.w * ex)
                 : "memory");
    if ((lane & 7) == 0)
        atomicAdd(&R.ssum[(size_t)d * NH + h], ex);
}

// ---------------------------------------------------------------------------
// Combiner: normalize per-relation aggregates, sum, gelu, tf32 round.
// ---------------------------------------------------------------------------
__global__ void combine_k(const float* __restrict__ aggr,
                          const float* __restrict__ ssum,
                          float* __restrict__ agg)
{
    int idx = blockIdx.x * blockDim.x + threadIdx.x;
    int total = (N0 + N1) * (HID / 4);
    if (idx >= total) return;
    int n = idx >> 5;
    int c4 = idx & 31;
    int h = c4 >> 3;
    float4 o;
    if (n < N0) {
        const float* ar = aggr + (size_t)N1 * HID;
        float inv = 1.f / (ssum[(size_t)N0 * NH * 1 + (size_t)n * NH + h] + 1e-16f);
        float4 v = reinterpret_cast<const float4*>(ar + (size_t)n * HID)[c4];
        o = make_float4(v.x * inv, v.y * inv, v.z * inv, v.w * inv);
    } else {
        int m = n - N0;
        const float* ar0 = aggr;
        const float* ar2 = aggr + (size_t)(N1 + N0) * HID;
        float inv0 = 1.f / (ssum[(size_t)m * NH + h] + 1e-16f);
        float inv2 = 1.f / (ssum[(size_t)N0 * NH * 2 + (size_t)m * NH + h] + 1e-16f);
        float4 v0 = reinterpret_cast<const float4*>(ar0 + (size_t)m * HID)[c4];
        float4 v2 = reinterpret_cast<const float4*>(ar2 + (size_t)m * HID)[c4];
        o = make_float4(v0.x * inv0 + v2.x * inv2, v0.y * inv0 + v2.y * inv2,
                        v0.z * inv0 + v2.z * inv2, v0.w * inv0 + v2.w * inv2);
    }
    o.x = __uint_as_float(f2tf32(gelu_exact(o.x)));
    o.y = __uint_as_float(f2tf32(gelu_exact(o.y)));
    o.z = __uint_as_float(f2tf32(gelu_exact(o.z)));
    o.w = __uint_as_float(f2tf32(gelu_exact(o.w)));
    reinterpret_cast<float4*>(agg + (size_t)n * HID)[c4] = o;
}

// ---------------------------------------------------------------------------
// Host orchestration
// ---------------------------------------------------------------------------
extern "C" void kernel_launch(void* const* d_in, const int* in_sizes, int n_in,
                              void* d_out, int out_size)
{
    const float* x0   = (const float*)d_in[0];
    const float* x1   = (const float*)d_in[1];
    const int* srcp[3] = {(const int*)d_in[2], (const int*)d_in[4], (const int*)d_in[6]};
    const int* dstp[3] = {(const int*)d_in[3], (const int*)d_in[5], (const int*)d_in[7]};
    const int  Ecnt[3] = {in_sizes[2], in_sizes[4], in_sizes[6]};
    const float* W_in = (const float*)d_in[8];
    const float* b_in = (const float*)d_in[9];
    const float* Wk   = (const float*)d_in[10];
    const float* bk   = (const float*)d_in[11];
    const float* Wq   = (const float*)d_in[12];
    const float* bq   = (const float*)d_in[13];
    const float* Wv   = (const float*)d_in[14];
    const float* bv   = (const float*)d_in[15];
    const float* Wa   = (const float*)d_in[16];
    const float* ba   = (const float*)d_in[17];
    const float* skip = (const float*)d_in[18];
    const float* a_rel = (const float*)d_in[19];
    const float* m_rel = (const float*)d_in[20];
    const float* p_rel = (const float*)d_in[21];

    float* out = (float*)d_out;
    const int OW = HID * (NL + 1);       // 384
    float* y0 = out;
    float* y1 = out + (size_t)N0 * OW;

    float *qkv0, *qkv1, *agg, *aggr, *wcat0, *wcat1, *bcat0, *bcat1, *win, *wa;
    int *deg, *rowptr, *csr_src, *csr_dst;
    cudaGetSymbolAddress((void**)&qkv0,    g_qkv0);
    cudaGetSymbolAddress((void**)&qkv1,    g_qkv1);
    cudaGetSymbolAddress((void**)&agg,     g_agg);
    cudaGetSymbolAddress((void**)&aggr,    g_aggr);
    cudaGetSymbolAddress((void**)&deg,     g_deg);
    cudaGetSymbolAddress((void**)&rowptr,  g_rowptr);
    cudaGetSymbolAddress((void**)&csr_src, g_csr_src);
    cudaGetSymbolAddress((void**)&csr_dst, g_csr_dst);
    cudaGetSymbolAddress((void**)&wcat0,   g_wcat0);
    cudaGetSymbolAddress((void**)&wcat1,   g_wcat1);
    cudaGetSymbolAddress((void**)&bcat0,   g_bcat0);
    cudaGetSymbolAddress((void**)&bcat1,   g_bcat1);
    cudaGetSymbolAddress((void**)&win,     g_win);
    cudaGetSymbolAddress((void**)&wa,      g_wa);
    float* ssum = aggr + AGGR_FLOATS;

    cudaFuncSetAttribute(gemm_tc<0,1>, cudaFuncAttributeMaxDynamicSharedMemorySize, GEMM_SMEM);
    cudaFuncSetAttribute(gemm_tc<1,1>, cudaFuncAttributeMaxDynamicSharedMemorySize, GEMM_SMEM);
    cudaFuncSetAttribute(gemm_tc<2,0>, cudaFuncAttributeMaxDynamicSharedMemorySize, GEMM_SMEM);

    const dim3 g0((N0 + GBM - 1) / GBM);
    const dim3 g1((N1 + GBM - 1) / GBM);

    // ---- CSR-order edge sort (once; edges constant across layers)
    CsrP CP;
    for (int r = 0; r < 3; r++) { CP.src[r] = srcp[r]; CP.dst[r] = dstp[r]; }
    CP.segbase[0] = 0; CP.segbase[1] = N1; CP.segbase[2] = N1 + N0;
    CP.off1 = Ecnt[0]; CP.off2 = Ecnt[0] + Ecnt[1];
    CP.total = Ecnt[0] + Ecnt[1] + Ecnt[2];
    CP.deg = deg; CP.rowptr = rowptr; CP.csr_src = csr_src; CP.csr_dst = csr_dst;
    int hBlocks = (CP.total + 255) / 256;
    cudaMemsetAsync(deg, 0, NSEG * sizeof(int), 0);
    hist_k<<<hBlocks, 256>>>(CP);
    scan_k<<<1, 1024>>>(deg, rowptr, NSEG);
    cudaMemsetAsync(deg, 0, NSEG * sizeof(int), 0);
    scatter_k<<<hBlocks, 256>>>(CP);

    // ---- ALL weight prep in one launch (22 sections: 2 win + per-layer 10)
    {
        WPrepN P;
        P.s[0] = {W_in,             b_in, nullptr, win,             nullptr, HID};
        P.s[1] = {W_in + HID * HID, b_in, nullptr, win + HID * HID, nullptr, HID};
        for (int l = 0; l < NL; l++) {
            float* wc0 = wcat0 + (size_t)l * HID * LD0;
            float* wc1 = wcat1 + (size_t)l * HID * LD1;
            float* bc0 = bcat0 + (size_t)l * LD0;
            float* bc1 = bcat1 + (size_t)l * LD1;
            float* wal = wa + (size_t)l * 2 * HID * HID;
            const float* WkL0 = Wk + (size_t)(l * 2 + 0) * HID * HID;
            const float* WkL1 = Wk + (size_t)(l * 2 + 1) * HID * HID;
            const float* WvL0 = Wv + (size_t)(l * 2 + 0) * HID * HID;
            const float* WvL1 = Wv + (size_t)(l * 2 + 1) * HID * HID;
            const float* ar0 = a_rel + (size_t)(l * 3 + 0) * NH * HD * HD;
            const float* ar1 = a_rel + (size_t)(l * 3 + 1) * NH * HD * HD;
            const float* ar2 = a_rel + (size_t)(l * 3 + 2) * NH * HD * HD;
            const float* mr0 = m_rel + (size_t)(l * 3 + 0) * NH * HD * HD;
            const float* mr1 = m_rel + (size_t)(l * 3 + 1) * NH * HD * HD;
            const float* mr2 = m_rel + (size_t)(l * 3 + 2) * NH * HD * HD;
            int o = 2 + l * 10;
            P.s[o + 0] = {Wq + (size_t)(l*2+0)*HID*HID, bq + (l*2+0)*HID, nullptr, wc0,       bc0,       LD0};
            P.s[o + 1] = {WkL0, bk + (l*2+0)*HID, ar0, wc0 + 128, bc0 + 128, LD0};
            P.s[o + 2] = {WvL0, bv + (l*2+0)*HID, mr0, wc0 + 256, bc0 + 256, LD0};
            P.s[o + 3] = {Wq + (size_t)(l*2+1)*HID*HID, bq + (l*2+1)*HID, nullptr, wc1,       bc1,       LD1};
            P.s[o + 4] = {WkL1, bk + (l*2+1)*HID, ar1, wc1 + 128, bc1 + 128, LD1};
            P.s[o + 5] = {WvL1, bv + (l*2+1)*HID, mr1, wc1 + 256, bc1 + 256, LD1};
            P.s[o + 6] = {WkL1, bk + (l*2+1)*HID, ar2, wc1 + 384, bc1 + 384, LD1};
            P.s[o + 7] = {WvL1, bv + (l*2+1)*HID, mr2, wc1 + 512, bc1 + 512, LD1};
            P.s[o + 8] = {Wa + (size_t)(l*2+0)*HID*HID, nullptr, nullptr, wal,             nullptr, HID};
            P.s[o + 9] = {Wa + (size_t)(l*2+1)*HID*HID, nullptr, nullptr, wal + HID * HID, nullptr, HID};
        }
        prep_w_k<<<dim3(HID + 1, 22), HID>>>(P);
    }

    // ---- input projection
    gemm_tc<1,1><<<g0, 512, GEMM_SMEM>>>(x0, HID, win, HID, b_in, y0, OW, N0,
                                         nullptr, 0, nullptr);
    gemm_tc<1,1><<<g1, 512, GEMM_SMEM>>>(x1, HID, win + HID * HID, HID, b_in + HID,
                                         y1, OW, N1, nullptr, 0, nullptr);

    for (int l = 0; l < NL; l++) {
        const float* h0 = y0 + l * HID;  // lda = OW
        const float* h1 = y1 + l * HID;
        const float* wc0 = wcat0 + (size_t)l * HID * LD0;
        const float* wc1 = wcat1 + (size_t)l * HID * LD1;
        const float* bc0 = bcat0 + (size_t)l * LD0;
        const float* bc1 = bcat1 + (size_t)l * LD1;
        const float* wal = wa + (size_t)l * 2 * HID * HID;

        // ---- fused projections
        gemm_tc<0,1><<<dim3(g0.x, LD0 / GBN), 512, GEMM_SMEM>>>(
            h0, OW, wc0, LD0, bc0, qkv0, LD0, N0, nullptr, 0, nullptr);
        gemm_tc<0,1><<<dim3(g1.x, LD1 / GBN), 512, GEMM_SMEM>>>(
            h1, OW, wc1, LD1, bc1, qkv1, LD1, N1, nullptr, 0, nullptr);

        // one memset covers aggr + ssum (contiguous)
        cudaMemsetAsync(aggr, 0, (AGGR_FLOATS + SSUM_FLOATS) * sizeof(float), 0);

        // ---- single-pass fused edge stage over dst-sorted edges
        Edge3 EP;
        const float* qd_tab[3]  = {qkv1,        qkv0,        qkv1};
        const int    ldq_tab[3] = {LD1,         LD0,         LD1};
        const float* kr_tab[3]  = {qkv0 + 128,  qkv1 + 128,  qkv1 + 384};
        const float* vr_tab[3]  = {qkv0 + 256,  qkv1 + 256,  qkv1 + 512};
        const int    lds_tab[3] = {LD0,         LD1,         LD1};
        float* aggr_tab[3] = {aggr,
                              aggr + (size_t)N1 * HID,
                              aggr + (size_t)(N1 + N0) * HID};
        const int ebase[3] = {0, Ecnt[0], Ecnt[0] + Ecnt[1]};
        for (int r = 0; r < 3; r++) {
            EP.r[r].src  = csr_src + ebase[r];
            EP.r[r].dst  = csr_dst + ebase[r];
            EP.r[r].q    = qd_tab[r];  EP.r[r].ldq = ldq_tab[r];
            EP.r[r].kr   = kr_tab[r];  EP.r[r].ldk = lds_tab[r];
            EP.r[r].vr   = vr_tab[r];  EP.r[r].ldv = lds_tab[r];
            EP.r[r].prel = p_rel + (size_t)(l * 3 + r) * NH;
            EP.r[r].ssum = ssum + (size_t)r * N0 * NH;
            EP.r[r].aggr = aggr_tab[r];
        }
        EP.off1 = Ecnt[0];
        EP.off2 = Ecnt[0] + Ecnt[1];
        EP.total = Ecnt[0] + Ecnt[1] + Ecnt[2];
        int eBlocks = (EP.total + 7) / 8;
        edge_fused_k<<<eBlocks, 256>>>(EP);

        // ---- combine + gelu + round
        int cThreads = (N0 + N1) * (HID / 4);
        combine_k<<<(cThreads + 255) / 256, 256>>>(aggr, ssum, agg);

        // ---- output projection + skip blend
        gemm_tc<2,0><<<g0, 512, GEMM_SMEM>>>(agg, HID, wal, HID,
                                             ba + (l * 2 + 0) * HID,
                                             y0 + (l + 1) * HID, OW, N0,
                                             h0, OW, skip + l * 2 + 0);
        gemm_tc<2,0><<<g1, 512, GEMM_SMEM>>>(agg + (size_t)N0 * HID, HID,
                                             wal + HID * HID, HID,
                                             ba + (l * 2 + 1) * HID,
                                             y1 + (l + 1) * HID, OW, N1,
                                             h1, OW, skip + l * 2 + 1);
    }
}

// round 12
// speedup vs baseline: 1.4573x; 1.1598x over previous
#include <cuda_runtime.h>
#include <cuda_bf16.h>
#include <math.h>
#include <stdint.h>

// ---------------------------------------------------------------------------
// Problem constants
// ---------------------------------------------------------------------------
#define N0 100000
#define N1 50000
#define EMAX 200000
#define HID 128
#define NH 4
#define HD 32
#define NL 2

#define LD0 384   // type0: Q | K_r0 | V_r0
#define LD1 640   // type1: Q | K_r1 | V_r1 | K_r2 | V_r2

#define NB0 ((N0 + 127) / 128)   // 782
#define NB1 ((N1 + 127) / 128)   // 391

// aggr layout: r0 (N1 rows) @0, r1 (N0 rows) @N1*HID, r2 (N1 rows) @(N1+N0)*HID
// ssum lives directly after aggr so one memset clears both.
#define AGGR_FLOATS ((size_t)(N0 + 2 * N1) * HID)
#define SSUM_FLOATS ((size_t)3 * N0 * NH)

// ---------------------------------------------------------------------------
// Static device scratch
// ---------------------------------------------------------------------------
__device__ float g_qkv0[(size_t)N0 * LD0];
__device__ float g_qkv1[(size_t)N1 * LD1];
__device__ float g_agg[(size_t)(N0 + N1) * HID];
__device__ float g_aggr[AGGR_FLOATS + SSUM_FLOATS];
__device__ float g_wcat0[NL * HID * LD0];
__device__ float g_wcat1[NL * HID * LD1];
__device__ float g_bcat0[NL * LD0];
__device__ float g_bcat1[NL * LD1];
__device__ float g_win[2 * HID * HID];
__device__ float g_wa[NL * 2 * HID * HID];

// ---------------------------------------------------------------------------
// Helpers
// ---------------------------------------------------------------------------
__device__ __forceinline__ float gelu_exact(float x) {
    return 0.5f * x * (1.0f + erff(x * 0.7071067811865476f));
}
__device__ __forceinline__ unsigned f2tf32(float f) {
    unsigned u;
    asm("cvt.rna.tf32.f32 %0, %1;" : "=r"(u) : "f"(f));
    return u;
}
__device__ __forceinline__ void mma_tf32(float* c, const unsigned* a, const unsigned* b) {
    asm("mma.sync.aligned.m16n8k8.row.col.f32.tf32.tf32.f32 "
        "{%0,%1,%2,%3}, {%4,%5,%6,%7}, {%8,%9}, {%0,%1,%2,%3};"
        : "+f"(c[0]), "+f"(c[1]), "+f"(c[2]), "+f"(c[3])
        : "r"(a[0]), "r"(a[1]), "r"(a[2]), "r"(a[3]), "r"(b[0]), "r"(b[1]));
}
__device__ __forceinline__ void cpa16(float* dst, const float* src) {
    unsigned d = (unsigned)__cvta_generic_to_shared(dst);
    asm volatile("cp.async.cg.shared.global [%0], [%1], 16;" :: "r"(d), "l"(src));
}
__device__ __forceinline__ void cp_commit() { asm volatile("cp.async.commit_group;"); }
template <int N>
__device__ __forceinline__ void cp_wait() {
    asm volatile("cp.async.wait_group %0;" :: "n"(N));
}

// ---------------------------------------------------------------------------
// Paired TF32 TC GEMM: one launch covers both node types. Block side chosen
// by blockIdx.x range. cp.async 3-stage, 128x128x16 tiles, 512 threads.
//   EPI: 0 none, 1 relu, 2 skip-blend with hprev   CVT_A: round A at frag load
// ---------------------------------------------------------------------------
#define GBM 128
#define GBN 128
#define AS_LD 20
#define BS_LD 136
#define A_STG (128 * AS_LD)
#define B_STG (16 * BS_LD)
#define GEMM_SMEM (3 * (A_STG + B_STG) * 4)

struct GemmSide {
    const float* A; int lda;
    const float* B; int ldb;
    const float* bias;
    float* C; int ldc;
    int M; int nby;
    const float* hprev; int ldh;
    const float* skipPtr;
};
struct GemmPair { GemmSide s[2]; int nb0; };

template <int EPI, int CVT_A>
__global__ __launch_bounds__(512, 2) void gemm_tc(GemmPair P)
{
    extern __shared__ float smemf[];
    float* AsBase = smemf;
    float* BsBase = smemf + 3 * A_STG;

    const int side = (blockIdx.x >= (unsigned)P.nb0);
    const GemmSide S = P.s[side];
    const int bx = side ? (blockIdx.x - P.nb0) : blockIdx.x;
    if ((int)blockIdx.y >= S.nby) return;

    const int tid  = threadIdx.x;
    const int wid  = tid >> 5;
    const int lane = tid & 31;
    const int row0 = bx * GBM;
    const int col0 = blockIdx.y * GBN;
    const int wm0  = (wid >> 2) * 32;
    const int wn0  = (wid & 3) * 32;
    const int g    = lane >> 2;
    const int tig  = lane & 3;

    const int rA = tid >> 2, kcA = (tid & 3) << 2;
    const int kB = tid >> 5, ncB = (tid & 31) << 2;
    int gArow = row0 + rA; if (gArow >= S.M) gArow = S.M - 1;
    const float* gA = S.A + (size_t)gArow * S.lda + kcA;
    const float* gB = S.B + (size_t)kB * S.ldb + col0 + ncB;
    const int ldb = S.ldb;

    auto stage_load = [&](int s, int k0) {
        cpa16(AsBase + s * A_STG + rA * AS_LD + kcA, gA + k0);
        cpa16(BsBase + s * B_STG + kB * BS_LD + ncB, gB + (size_t)k0 * ldb);
    };

    stage_load(0, 0);  cp_commit();
    stage_load(1, 16); cp_commit();

    float acc[2][4][4];
#pragma unroll
    for (int i = 0; i < 2; i++)
#pragma unroll
        for (int j = 0; j < 4; j++)
#pragma unroll
            for (int q = 0; q < 4; q++) acc[i][j][q] = 0.f;

#pragma unroll
    for (int kt = 0; kt < 8; kt++) {
        cp_wait<1>();
        __syncthreads();
        if (kt + 2 < 8) stage_load((kt + 2) % 3, (kt + 2) * 16);
        cp_commit();

        const float* Ast = AsBase + (kt % 3) * A_STG;
        const float* Bst = BsBase + (kt % 3) * B_STG;
#pragma unroll
        for (int k8 = 0; k8 < 2; k8++) {
            const int kk = k8 * 8;
            unsigned aR[2][4], bR[4][2];
#pragma unroll
            for (int mt = 0; mt < 2; mt++) {
                int m = wm0 + mt * 16 + g;
                float a0 = Ast[(size_t)m * AS_LD + kk + tig];
                float a1 = Ast[(size_t)(m + 8) * AS_LD + kk + tig];
                float a2 = Ast[(size_t)m * AS_LD + kk + tig + 4];
                float a3 = Ast[(size_t)(m + 8) * AS_LD + kk + tig + 4];
                if (CVT_A) {
                    aR[mt][0] = f2tf32(a0); aR[mt][1] = f2tf32(a1);
                    aR[mt][2] = f2tf32(a2); aR[mt][3] = f2tf32(a3);
                } else {
                    aR[mt][0] = __float_as_uint(a0); aR[mt][1] = __float_as_uint(a1);
                    aR[mt][2] = __float_as_uint(a2); aR[mt][3] = __float_as_uint(a3);
                }
            }
#pragma unroll
            for (int nt = 0; nt < 4; nt++) {
                int n = wn0 + nt * 8 + g;
                bR[nt][0] = __float_as_uint(Bst[(size_t)(kk + tig) * BS_LD + n]);
                bR[nt][1] = __float_as_uint(Bst[(size_t)(kk + tig + 4) * BS_LD + n]);
            }
#pragma unroll
            for (int mt = 0; mt < 2; mt++)
#pragma unroll
                for (int nt = 0; nt < 4; nt++)
                    mma_tf32(acc[mt][nt], aR[mt], bR[nt]);
        }
    }

    float sgate = 0.f;
    if (EPI == 2) sgate = 1.f / (1.f + expf(-(*S.skipPtr)));

#pragma unroll
    for (int mt = 0; mt < 2; mt++) {
#pragma unroll
        for (int rr = 0; rr < 2; rr++) {
            int grow = row0 + wm0 + mt * 16 + g + rr * 8;
            if (grow >= S.M) continue;
#pragma unroll
            for (int nt = 0; nt < 4; nt++) {
                int col = col0 + wn0 + nt * 8 + 2 * tig;
                float v0 = acc[mt][nt][rr * 2 + 0] + S.bias[col];
                float v1 = acc[mt][nt][rr * 2 + 1] + S.bias[col + 1];
                if (EPI == 1) { v0 = fmaxf(v0, 0.f); v1 = fmaxf(v1, 0.f); }
                if (EPI == 2) {
                    const float* hp = S.hprev + (size_t)grow * S.ldh + col;
                    v0 = sgate * v0 + (1.f - sgate) * hp[0];
                    v1 = sgate * v1 + (1.f - sgate) * hp[1];
                }
                *reinterpret_cast<float2*>(S.C + (size_t)grow * S.ldc + col) =
                    make_float2(v0, v1);
            }
        }
    }
}

// ---------------------------------------------------------------------------
// Weight prep: 22 sections in one launch. A==nullptr -> tf32-rounded copy.
// ---------------------------------------------------------------------------
struct WPrepSec {
    const float* W; const float* b; const float* A;
    float* Wd; float* bd; int ld;
};
struct WPrepN { WPrepSec s[22]; };

__global__ void prep_w_k(WPrepN P)
{
    WPrepSec p = P.s[blockIdx.y];
    int col = threadIdx.x;
    int i = blockIdx.x;
    if (p.A == nullptr) {
        if (i < HID)
            p.Wd[(size_t)i * p.ld + col] =
                __uint_as_float(f2tf32(p.W[(size_t)i * HID + col]));
        else if (p.bd) p.bd[col] = p.b[col];
        return;
    }
    int h = col >> 5, e = col & 31;
    const float* Ah = p.A + h * HD * HD;
    if (i < HID) {
        const float* wrow = p.W + (size_t)i * HID + h * HD;
        float acc = 0.f;
#pragma unroll
        for (int d = 0; d < HD; d++) acc = fmaf(wrow[d], Ah[d * HD + e], acc);
        p.Wd[(size_t)i * p.ld + col] = __uint_as_float(f2tf32(acc));
    } else if (p.bd) {
        const float* brow = p.b + h * HD;
        float acc = 0.f;
#pragma unroll
        for (int d = 0; d < HD; d++) acc = fmaf(brow[d], Ah[d * HD + e], acc);
        p.bd[col] = acc;
    }
}

// ---------------------------------------------------------------------------
// Single-pass fused edge kernel (warp per edge, all 3 relations per launch)
// ---------------------------------------------------------------------------
struct EdgeRel {
    const int* src; const int* dst;
    const float* q; int ldq;
    const float* kr; int ldk;
    const float* vr; int ldv;
    const float* prel;
    float* ssum; float* aggr;
};
struct Edge3 { EdgeRel r[3]; int off1, off2, total; };

__global__ void edge_fused_k(Edge3 P)
{
    int w = blockIdx.x * (blockDim.x >> 5) + (threadIdx.x >> 5);
    if (w >= P.total) return;
    int lane = threadIdx.x & 31;
    int ri = (w >= P.off1) + (w >= P.off2);
    int base = ri == 0 ? 0 : (ri == 1 ? P.off1 : P.off2);
    EdgeRel R = P.r[ri];
    int e = w - base;
    int s = __ldg(&R.src[e]), d = __ldg(&R.dst[e]);
    float4 qv = *reinterpret_cast<const float4*>(R.q + (size_t)d * R.ldq + lane * 4);
    float4 kv = *reinterpret_cast<const float4*>(R.kr + (size_t)s * R.ldk + lane * 4);
    float acc = qv.x * kv.x + qv.y * kv.y + qv.z * kv.z + qv.w * kv.w;
    acc += __shfl_xor_sync(0xffffffffu, acc, 1);
    acc += __shfl_xor_sync(0xffffffffu, acc, 2);
    acc += __shfl_xor_sync(0xffffffffu, acc, 4);
    int h = lane >> 3;
    float a = acc * __ldg(&R.prel[h]) * 0.17677669529663689f; // 1/sqrt(32)
    float ex = expf(a);
    float4 v = *reinterpret_cast<const float4*>(R.vr + (size_t)s * R.ldv + lane * 4);
    float* p = R.aggr + (size_t)d * HID + lane * 4;
    asm volatile("red.global.add.v4.f32 [%0], {%1,%2,%3,%4};"
                 :: "l"(p), "f"(v.x * ex), "f"(v.y * ex),
                    "f"(v.z * ex), "f"(v.w * ex)
                 : "memory");
    if ((lane & 7) == 0)
        atomicAdd(&R.ssum[(size_t)d * NH + h], ex);
}

// ---------------------------------------------------------------------------
// Combiner: normalize per-relation aggregates, sum, gelu, tf32 round.
// ---------------------------------------------------------------------------
__global__ void combine_k(const float* __restrict__ aggr,
                          const float* __restrict__ ssum,
                          float* __restrict__ agg)
{
    int idx = blockIdx.x * blockDim.x + threadIdx.x;
    int total = (N0 + N1) * (HID / 4);
    if (idx >= total) return;
    int n = idx >> 5;
    int c4 = idx & 31;
    int h = c4 >> 3;
    float4 o;
    if (n < N0) {
        const float* ar = aggr + (size_t)N1 * HID;
        float inv = 1.f / (ssum[(size_t)N0 * NH * 1 + (size_t)n * NH + h] + 1e-16f);
        float4 v = reinterpret_cast<const float4*>(ar + (size_t)n * HID)[c4];
        o = make_float4(v.x * inv, v.y * inv, v.z * inv, v.w * inv);
    } else {
        int m = n - N0;
        const float* ar0 = aggr;
        const float* ar2 = aggr + (size_t)(N1 + N0) * HID;
        float inv0 = 1.f / (ssum[(size_t)m * NH + h] + 1e-16f);
        float inv2 = 1.f / (ssum[(size_t)N0 * NH * 2 + (size_t)m * NH + h] + 1e-16f);
        float4 v0 = reinterpret_cast<const float4*>(ar0 + (size_t)m * HID)[c4];
        float4 v2 = reinterpret_cast<const float4*>(ar2 + (size_t)m * HID)[c4];
        o = make_float4(v0.x * inv0 + v2.x * inv2, v0.y * inv0 + v2.y * inv2,
                        v0.z * inv0 + v2.z * inv2, v0.w * inv0 + v2.w * inv2);
    }
    o.x = __uint_as_float(f2tf32(gelu_exact(o.x)));
    o.y = __uint_as_float(f2tf32(gelu_exact(o.y)));
    o.z = __uint_as_float(f2tf32(gelu_exact(o.z)));
    o.w = __uint_as_float(f2tf32(gelu_exact(o.w)));
    reinterpret_cast<float4*>(agg + (size_t)n * HID)[c4] = o;
}

// ---------------------------------------------------------------------------
// Host orchestration
// ---------------------------------------------------------------------------
extern "C" void kernel_launch(void* const* d_in, const int* in_sizes, int n_in,
                              void* d_out, int out_size)
{
    const float* x0   = (const float*)d_in[0];
    const float* x1   = (const float*)d_in[1];
    const int* srcp[3] = {(const int*)d_in[2], (const int*)d_in[4], (const int*)d_in[6]};
    const int* dstp[3] = {(const int*)d_in[3], (const int*)d_in[5], (const int*)d_in[7]};
    const int  Ecnt[3] = {in_sizes[2], in_sizes[4], in_sizes[6]};
    const float* W_in = (const float*)d_in[8];
    const float* b_in = (const float*)d_in[9];
    const float* Wk   = (const float*)d_in[10];
    const float* bk   = (const float*)d_in[11];
    const float* Wq   = (const float*)d_in[12];
    const float* bq   = (const float*)d_in[13];
    const float* Wv   = (const float*)d_in[14];
    const float* bv   = (const float*)d_in[15];
    const float* Wa   = (const float*)d_in[16];
    const float* ba   = (const float*)d_in[17];
    const float* skip = (const float*)d_in[18];
    const float* a_rel = (const float*)d_in[19];
    const float* m_rel = (const float*)d_in[20];
    const float* p_rel = (const float*)d_in[21];

    float* out = (float*)d_out;
    const int OW = HID * (NL + 1);       // 384
    float* y0 = out;
    float* y1 = out + (size_t)N0 * OW;

    float *qkv0, *qkv1, *agg, *aggr, *wcat0, *wcat1, *bcat0, *bcat1, *win, *wa;
    cudaGetSymbolAddress((void**)&qkv0,  g_qkv0);
    cudaGetSymbolAddress((void**)&qkv1,  g_qkv1);
    cudaGetSymbolAddress((void**)&agg,   g_agg);
    cudaGetSymbolAddress((void**)&aggr,  g_aggr);
    cudaGetSymbolAddress((void**)&wcat0, g_wcat0);
    cudaGetSymbolAddress((void**)&wcat1, g_wcat1);
    cudaGetSymbolAddress((void**)&bcat0, g_bcat0);
    cudaGetSymbolAddress((void**)&bcat1, g_bcat1);
    cudaGetSymbolAddress((void**)&win,   g_win);
    cudaGetSymbolAddress((void**)&wa,    g_wa);
    float* ssum = aggr + AGGR_FLOATS;

    cudaFuncSetAttribute(gemm_tc<0,1>, cudaFuncAttributeMaxDynamicSharedMemorySize, GEMM_SMEM);
    cudaFuncSetAttribute(gemm_tc<1,1>, cudaFuncAttributeMaxDynamicSharedMemorySize, GEMM_SMEM);
    cudaFuncSetAttribute(gemm_tc<2,0>, cudaFuncAttributeMaxDynamicSharedMemorySize, GEMM_SMEM);

    // ---- ALL weight prep in one launch (22 sections)
    {
        WPrepN P;
        P.s[0] = {W_in,             b_in, nullptr, win,             nullptr, HID};
        P.s[1] = {W_in + HID * HID, b_in, nullptr, win + HID * HID, nullptr, HID};
        for (int l = 0; l < NL; l++) {
            float* wc0 = wcat0 + (size_t)l * HID * LD0;
            float* wc1 = wcat1 + (size_t)l * HID * LD1;
            float* bc0 = bcat0 + (size_t)l * LD0;
            float* bc1 = bcat1 + (size_t)l * LD1;
            float* wal = wa + (size_t)l * 2 * HID * HID;
            const float* WkL0 = Wk + (size_t)(l * 2 + 0) * HID * HID;
            const float* WkL1 = Wk + (size_t)(l * 2 + 1) * HID * HID;
            const float* WvL0 = Wv + (size_t)(l * 2 + 0) * HID * HID;
            const float* WvL1 = Wv + (size_t)(l * 2 + 1) * HID * HID;
            const float* ar0 = a_rel + (size_t)(l * 3 + 0) * NH * HD * HD;
            const float* ar1 = a_rel + (size_t)(l * 3 + 1) * NH * HD * HD;
            const float* ar2 = a_rel + (size_t)(l * 3 + 2) * NH * HD * HD;
            const float* mr0 = m_rel + (size_t)(l * 3 + 0) * NH * HD * HD;
            const float* mr1 = m_rel + (size_t)(l * 3 + 1) * NH * HD * HD;
            const float* mr2 = m_rel + (size_t)(l * 3 + 2) * NH * HD * HD;
            int o = 2 + l * 10;
            P.s[o + 0] = {Wq + (size_t)(l*2+0)*HID*HID, bq + (l*2+0)*HID, nullptr, wc0,       bc0,       LD0};
            P.s[o + 1] = {WkL0, bk + (l*2+0)*HID, ar0, wc0 + 128, bc0 + 128, LD0};
            P.s[o + 2] = {WvL0, bv + (l*2+0)*HID, mr0, wc0 + 256, bc0 + 256, LD0};
            P.s[o + 3] = {Wq + (size_t)(l*2+1)*HID*HID, bq + (l*2+1)*HID, nullptr, wc1,       bc1,       LD1};
            P.s[o + 4] = {WkL1, bk + (l*2+1)*HID, ar1, wc1 + 128, bc1 + 128, LD1};
            P.s[o + 5] = {WvL1, bv + (l*2+1)*HID, mr1, wc1 + 256, bc1 + 256, LD1};
            P.s[o + 6] = {WkL1, bk + (l*2+1)*HID, ar2, wc1 + 384, bc1 + 384, LD1};
            P.s[o + 7] = {WvL1, bv + (l*2+1)*HID, mr2, wc1 + 512, bc1 + 512, LD1};
            P.s[o + 8] = {Wa + (size_t)(l*2+0)*HID*HID, nullptr, nullptr, wal,             nullptr, HID};
            P.s[o + 9] = {Wa + (size_t)(l*2+1)*HID*HID, nullptr, nullptr, wal + HID * HID, nullptr, HID};
        }
        prep_w_k<<<dim3(HID + 1, 22), HID>>>(P);
    }

    // ---- input projection (both types, one launch)
    {
        GemmPair P;
        P.nb0 = NB0;
        P.s[0] = {x0, HID, win,             HID, b_in,       y0, OW, N0, 1, nullptr, 0, nullptr};
        P.s[1] = {x1, HID, win + HID * HID, HID, b_in + HID, y1, OW, N1, 1, nullptr, 0, nullptr};
        gemm_tc<1,1><<<dim3(NB0 + NB1, 1), 512, GEMM_SMEM>>>(P);
    }

    for (int l = 0; l < NL; l++) {
        const float* h0 = y0 + l * HID;  // lda = OW
        const float* h1 = y1 + l * HID;
        const float* wc0 = wcat0 + (size_t)l * HID * LD0;
        const float* wc1 = wcat1 + (size_t)l * HID * LD1;
        const float* bc0 = bcat0 + (size_t)l * LD0;
        const float* bc1 = bcat1 + (size_t)l * LD1;
        const float* wal = wa + (size_t)l * 2 * HID * HID;

        // ---- fused qkv projections (both types, one launch, grid.y = 5)
        {
            GemmPair P;
            P.nb0 = NB0;
            P.s[0] = {h0, OW, wc0, LD0, bc0, qkv0, LD0, N0, LD0 / GBN, nullptr, 0, nullptr};
            P.s[1] = {h1, OW, wc1, LD1, bc1, qkv1, LD1, N1, LD1 / GBN, nullptr, 0, nullptr};
            gemm_tc<0,1><<<dim3(NB0 + NB1, LD1 / GBN), 512, GEMM_SMEM>>>(P);
        }

        // one memset covers aggr + ssum (contiguous)
        cudaMemsetAsync(aggr, 0, (AGGR_FLOATS + SSUM_FLOATS) * sizeof(float), 0);

        // ---- single-pass fused edge stage (original edge order)
        Edge3 EP;
        const float* qd_tab[3]  = {qkv1,        qkv0,        qkv1};
        const int    ldq_tab[3] = {LD1,         LD0,         LD1};
        const float* kr_tab[3]  = {qkv0 + 128,  qkv1 + 128,  qkv1 + 384};
        const float* vr_tab[3]  = {qkv0 + 256,  qkv1 + 256,  qkv1 + 512};
        const int    lds_tab[3] = {LD0,         LD1,         LD1};
        float* aggr_tab[3] = {aggr,
                              aggr + (size_t)N1 * HID,
                              aggr + (size_t)(N1 + N0) * HID};
        for (int r = 0; r < 3; r++) {
            EP.r[r].src  = srcp[r];
            EP.r[r].dst  = dstp[r];
            EP.r[r].q    = qd_tab[r];  EP.r[r].ldq = ldq_tab[r];
            EP.r[r].kr   = kr_tab[r];  EP.r[r].ldk = lds_tab[r];
            EP.r[r].vr   = vr_tab[r];  EP.r[r].ldv = lds_tab[r];
            EP.r[r].prel = p_rel + (size_t)(l * 3 + r) * NH;
            EP.r[r].ssum = ssum + (size_t)r * N0 * NH;
            EP.r[r].aggr = aggr_tab[r];
        }
        EP.off1 = Ecnt[0];
        EP.off2 = Ecnt[0] + Ecnt[1];
        EP.total = Ecnt[0] + Ecnt[1] + Ecnt[2];
        int eBlocks = (EP.total + 7) / 8;
        edge_fused_k<<<eBlocks, 256>>>(EP);

        // ---- combine + gelu + round
        int cThreads = (N0 + N1) * (HID / 4);
        combine_k<<<(cThreads + 255) / 256, 256>>>(aggr, ssum, agg);

        // ---- output projection + skip blend (both types, one launch)
        {
            GemmPair P;
            P.nb0 = NB0;
            P.s[0] = {agg, HID, wal, HID, ba + (l * 2 + 0) * HID,
                      y0 + (l + 1) * HID, OW, N0, 1, h0, OW, skip + l * 2 + 0};
            P.s[1] = {agg + (size_t)N0 * HID, HID, wal + HID * HID, HID,
                      ba + (l * 2 + 1) * HID,
                      y1 + (l + 1) * HID, OW, N1, 1, h1, OW, skip + l * 2 + 1};
            gemm_tc<2,0><<<dim3(NB0 + NB1, 1), 512, GEMM_SMEM>>>(P);
        }
    }
}

// round 13
// speedup vs baseline: 1.5156x; 1.0400x over previous
#include <cuda_runtime.h>
#include <cuda_fp16.h>
#include <math.h>
#include <stdint.h>

// ---------------------------------------------------------------------------
// Problem constants
// ---------------------------------------------------------------------------
#define N0 100000
#define N1 50000
#define HID 128
#define NH 4
#define HD 32
#define NL 2

#define LD0 384   // type0 weights: Q | K_r0 | V_r0
#define LD1 640   // type1 weights: Q | K_r1 | V_r1 | K_r2 | V_r2
#define KV0 256   // halves per type0 kv row (k@0, v@128)
#define KV1 512   // halves per type1 kv row (k1@0, v1@128, k2@256, v2@384)

#define NB0 ((N0 + 127) / 128)
#define NB1 ((N1 + 127) / 128)

#define AGGR_FLOATS ((size_t)(N0 + 2 * N1) * HID)
#define SSUM_FLOATS ((size_t)3 * N0 * NH)

// ---------------------------------------------------------------------------
// Static device scratch
// ---------------------------------------------------------------------------
__device__ float  g_q0[(size_t)N0 * HID];
__device__ float  g_q1[(size_t)N1 * HID];
__device__ __half g_kv0[(size_t)N0 * KV0];
__device__ __half g_kv1[(size_t)N1 * KV1];
__device__ float  g_agg[(size_t)(N0 + N1) * HID];
__device__ float  g_aggr[AGGR_FLOATS + SSUM_FLOATS];
__device__ float  g_wcat0[NL * HID * LD0];
__device__ float  g_wcat1[NL * HID * LD1];
__device__ float  g_bcat0[NL * LD0];
__device__ float  g_bcat1[NL * LD1];
__device__ float  g_win[2 * HID * HID];
__device__ float  g_wa[NL * 2 * HID * HID];

// ---------------------------------------------------------------------------
// Helpers
// ---------------------------------------------------------------------------
__device__ __forceinline__ float gelu_exact(float x) {
    return 0.5f * x * (1.0f + erff(x * 0.7071067811865476f));
}
__device__ __forceinline__ unsigned f2tf32(float f) {
    unsigned u;
    asm("cvt.rna.tf32.f32 %0, %1;" : "=r"(u) : "f"(f));
    return u;
}
__device__ __forceinline__ void mma_tf32(float* c, const unsigned* a, const unsigned* b) {
    asm("mma.sync.aligned.m16n8k8.row.col.f32.tf32.tf32.f32 "
        "{%0,%1,%2,%3}, {%4,%5,%6,%7}, {%8,%9}, {%0,%1,%2,%3};"
        : "+f"(c[0]), "+f"(c[1]), "+f"(c[2]), "+f"(c[3])
        : "r"(a[0]), "r"(a[1]), "r"(a[2]), "r"(a[3]), "r"(b[0]), "r"(b[1]));
}
__device__ __forceinline__ void cpa16(float* dst, const float* src) {
    unsigned d = (unsigned)__cvta_generic_to_shared(dst);
    asm volatile("cp.async.cg.shared.global [%0], [%1], 16;" :: "r"(d), "l"(src));
}
__device__ __forceinline__ void cp_commit() { asm volatile("cp.async.commit_group;"); }
template <int N>
__device__ __forceinline__ void cp_wait() {
    asm volatile("cp.async.wait_group %0;" :: "n"(N));
}

// ---------------------------------------------------------------------------
// Paired TF32 TC GEMM. OUTH=1: blockIdx.y==0 -> fp32 into C (Q section);
// blockIdx.y>=1 -> fp16 into Ckv at column (col-128).
//   EPI: 0 none, 1 relu, 2 skip-blend with hprev   CVT_A: round A at frag load
// ---------------------------------------------------------------------------
#define GBM 128
#define GBN 128
#define AS_LD 20
#define BS_LD 136
#define A_STG (128 * AS_LD)
#define B_STG (16 * BS_LD)
#define GEMM_SMEM (3 * (A_STG + B_STG) * 4)

struct GemmSide {
    const float* A; int lda;
    const float* B; int ldb;
    const float* bias;
    float* C; int ldc;
    __half* Ckv; int ldkv;
    int M; int nby;
    const float* hprev; int ldh;
    const float* skipPtr;
};
struct GemmPair { GemmSide s[2]; int nb0; };

template <int EPI, int CVT_A, int OUTH>
__global__ __launch_bounds__(512, 2) void gemm_tc(GemmPair P)
{
    extern __shared__ float smemf[];
    float* AsBase = smemf;
    float* BsBase = smemf + 3 * A_STG;

    const int side = (blockIdx.x >= (unsigned)P.nb0);
    const GemmSide S = P.s[side];
    const int bx = side ? (blockIdx.x - P.nb0) : blockIdx.x;
    if ((int)blockIdx.y >= S.nby) return;

    const int tid  = threadIdx.x;
    const int wid  = tid >> 5;
    const int lane = tid & 31;
    const int row0 = bx * GBM;
    const int col0 = blockIdx.y * GBN;
    const int wm0  = (wid >> 2) * 32;
    const int wn0  = (wid & 3) * 32;
    const int g    = lane >> 2;
    const int tig  = lane & 3;

    const int rA = tid >> 2, kcA = (tid & 3) << 2;
    const int kB = tid >> 5, ncB = (tid & 31) << 2;
    int gArow = row0 + rA; if (gArow >= S.M) gArow = S.M - 1;
    const float* gA = S.A + (size_t)gArow * S.lda + kcA;
    const float* gB = S.B + (size_t)kB * S.ldb + col0 + ncB;
    const int ldb = S.ldb;

    auto stage_load = [&](int s, int k0) {
        cpa16(AsBase + s * A_STG + rA * AS_LD + kcA, gA + k0);
        cpa16(BsBase + s * B_STG + kB * BS_LD + ncB, gB + (size_t)k0 * ldb);
    };

    stage_load(0, 0);  cp_commit();
    stage_load(1, 16); cp_commit();

    float acc[2][4][4];
#pragma unroll
    for (int i = 0; i < 2; i++)
#pragma unroll
        for (int j = 0; j < 4; j++)
#pragma unroll
            for (int q = 0; q < 4; q++) acc[i][j][q] = 0.f;

#pragma unroll
    for (int kt = 0; kt < 8; kt++) {
        cp_wait<1>();
        __syncthreads();
        if (kt + 2 < 8) stage_load((kt + 2) % 3, (kt + 2) * 16);
        cp_commit();

        const float* Ast = AsBase + (kt % 3) * A_STG;
        const float* Bst = BsBase + (kt % 3) * B_STG;
#pragma unroll
        for (int k8 = 0; k8 < 2; k8++) {
            const int kk = k8 * 8;
            unsigned aR[2][4], bR[4][2];
#pragma unroll
            for (int mt = 0; mt < 2; mt++) {
                int m = wm0 + mt * 16 + g;
                float a0 = Ast[(size_t)m * AS_LD + kk + tig];
                float a1 = Ast[(size_t)(m + 8) * AS_LD + kk + tig];
                float a2 = Ast[(size_t)m * AS_LD + kk + tig + 4];
                float a3 = Ast[(size_t)(m + 8) * AS_LD + kk + tig + 4];
                if (CVT_A) {
                    aR[mt][0] = f2tf32(a0); aR[mt][1] = f2tf32(a1);
                    aR[mt][2] = f2tf32(a2); aR[mt][3] = f2tf32(a3);
                } else {
                    aR[mt][0] = __float_as_uint(a0); aR[mt][1] = __float_as_uint(a1);
                    aR[mt][2] = __float_as_uint(a2); aR[mt][3] = __float_as_uint(a3);
                }
            }
#pragma unroll
            for (int nt = 0; nt < 4; nt++) {
                int n = wn0 + nt * 8 + g;
                bR[nt][0] = __float_as_uint(Bst[(size_t)(kk + tig) * BS_LD + n]);
                bR[nt][1] = __float_as_uint(Bst[(size_t)(kk + tig + 4) * BS_LD + n]);
            }
#pragma unroll
            for (int mt = 0; mt < 2; mt++)
#pragma unroll
                for (int nt = 0; nt < 4; nt++)
                    mma_tf32(acc[mt][nt], aR[mt], bR[nt]);
        }
    }

    float sgate = 0.f;
    if (EPI == 2) sgate = 1.f / (1.f + expf(-(*S.skipPtr)));

    const bool halfOut = (OUTH == 1) && (blockIdx.y > 0);

#pragma unroll
    for (int mt = 0; mt < 2; mt++) {
#pragma unroll
        for (int rr = 0; rr < 2; rr++) {
            int grow = row0 + wm0 + mt * 16 + g + rr * 8;
            if (grow >= S.M) continue;
#pragma unroll
            for (int nt = 0; nt < 4; nt++) {
                int col = col0 + wn0 + nt * 8 + 2 * tig;
                float v0 = acc[mt][nt][rr * 2 + 0] + S.bias[col];
                float v1 = acc[mt][nt][rr * 2 + 1] + S.bias[col + 1];
                if (EPI == 1) { v0 = fmaxf(v0, 0.f); v1 = fmaxf(v1, 0.f); }
                if (EPI == 2) {
                    const float* hp = S.hprev + (size_t)grow * S.ldh + col;
                    v0 = sgate * v0 + (1.f - sgate) * hp[0];
                    v1 = sgate * v1 + (1.f - sgate) * hp[1];
                }
                if (halfOut) {
                    *reinterpret_cast<__half2*>(
                        S.Ckv + (size_t)grow * S.ldkv + (col - 128)) =
                        __floats2half2_rn(v0, v1);
                } else {
                    *reinterpret_cast<float2*>(S.C + (size_t)grow * S.ldc + col) =
                        make_float2(v0, v1);
                }
            }
        }
    }
}

// ---------------------------------------------------------------------------
// Weight prep: 22 sections in one launch. A==nullptr -> tf32-rounded copy.
// ---------------------------------------------------------------------------
struct WPrepSec {
    const float* W; const float* b; const float* A;
    float* Wd; float* bd; int ld;
};
struct WPrepN { WPrepSec s[22]; };

__global__ void prep_w_k(WPrepN P)
{
    WPrepSec p = P.s[blockIdx.y];
    int col = threadIdx.x;
    int i = blockIdx.x;
    if (p.A == nullptr) {
        if (i < HID)
            p.Wd[(size_t)i * p.ld + col] =
                __uint_as_float(f2tf32(p.W[(size_t)i * HID + col]));
        else if (p.bd) p.bd[col] = p.b[col];
        return;
    }
    int h = col >> 5, e = col & 31;
    const float* Ah = p.A + h * HD * HD;
    if (i < HID) {
        const float* wrow = p.W + (size_t)i * HID + h * HD;
        float acc = 0.f;
#pragma unroll
        for (int d = 0; d < HD; d++) acc = fmaf(wrow[d], Ah[d * HD + e], acc);
        p.Wd[(size_t)i * p.ld + col] = __uint_as_float(f2tf32(acc));
    } else if (p.bd) {
        const float* brow = p.b + h * HD;
        float acc = 0.f;
#pragma unroll
        for (int d = 0; d < HD; d++) acc = fmaf(brow[d], Ah[d * HD + e], acc);
        p.bd[col] = acc;
    }
}

// ---------------------------------------------------------------------------
// Single-pass fused edge kernel (warp per edge, all 3 relations per launch)
// q fp32; k,v fp16.
// ---------------------------------------------------------------------------
struct EdgeRel {
    const int* src; const int* dst;
    const float* q; int ldq;
    const __half* k; const __half* v; int ldkv;
    const float* prel;
    float* ssum; float* aggr;
};
struct Edge3 { EdgeRel r[3]; int off1, off2, total; };

__global__ void edge_fused_k(Edge3 P)
{
    int w = blockIdx.x * (blockDim.x >> 5) + (threadIdx.x >> 5);
    if (w >= P.total) return;
    int lane = threadIdx.x & 31;
    int ri = (w >= P.off1) + (w >= P.off2);
    int base = ri == 0 ? 0 : (ri == 1 ? P.off1 : P.off2);
    EdgeRel R = P.r[ri];
    int e = w - base;
    int s = __ldg(&R.src[e]), d = __ldg(&R.dst[e]);
    float4 qv = *reinterpret_cast<const float4*>(R.q + (size_t)d * R.ldq + lane * 4);
    uint2 kraw = *reinterpret_cast<const uint2*>(R.k + (size_t)s * R.ldkv + lane * 4);
    float2 k0 = __half22float2(*reinterpret_cast<__half2*>(&kraw.x));
    float2 k1 = __half22float2(*reinterpret_cast<__half2*>(&kraw.y));
    float acc = qv.x * k0.x + qv.y * k0.y + qv.z * k1.x + qv.w * k1.y;
    acc += __shfl_xor_sync(0xffffffffu, acc, 1);
    acc += __shfl_xor_sync(0xffffffffu, acc, 2);
    acc += __shfl_xor_sync(0xffffffffu, acc, 4);
    int h = lane >> 3;
    float a = acc * __ldg(&R.prel[h]) * 0.17677669529663689f; // 1/sqrt(32)
    float ex = expf(a);
    uint2 vraw = *reinterpret_cast<const uint2*>(R.v + (size_t)s * R.ldkv + lane * 4);
    float2 v0 = __half22float2(*reinterpret_cast<__half2*>(&vraw.x));
    float2 v1 = __half22float2(*reinterpret_cast<__half2*>(&vraw.y));
    float* p = R.aggr + (size_t)d * HID + lane * 4;
    asm volatile("red.global.add.v4.f32 [%0], {%1,%2,%3,%4};"
                 :: "l"(p), "f"(v0.x * ex), "f"(v0.y * ex),
                    "f"(v1.x * ex), "f"(v1.y * ex)
                 : "memory");
    if ((lane & 7) == 0)
        atomicAdd(&R.ssum[(size_t)d * NH + h], ex);
}

// ---------------------------------------------------------------------------
// Combiner: normalize per-relation aggregates, sum, gelu, tf32 round.
// ---------------------------------------------------------------------------
__global__ void combine_k(const float* __restrict__ aggr,
                          const float* __restrict__ ssum,
                          float* __restrict__ agg)
{
    int idx = blockIdx.x * blockDim.x + threadIdx.x;
    int total = (N0 + N1) * (HID / 4);
    if (idx >= total) return;
    int n = idx >> 5;
    int c4 = idx & 31;
    int h = c4 >> 3;
    float4 o;
    if (n < N0) {
        const float* ar = aggr + (size_t)N1 * HID;
        float inv = 1.f / (ssum[(size_t)N0 * NH * 1 + (size_t)n * NH + h] + 1e-16f);
        float4 v = reinterpret_cast<const float4*>(ar + (size_t)n * HID)[c4];
        o = make_float4(v.x * inv, v.y * inv, v.z * inv, v.w * inv);
    } else {
        int m = n - N0;
        const float* ar0 = aggr;
        const float* ar2 = aggr + (size_t)(N1 + N0) * HID;
        float inv0 = 1.f / (ssum[(size_t)m * NH + h] + 1e-16f);
        float inv2 = 1.f / (ssum[(size_t)N0 * NH * 2 + (size_t)m * NH + h] + 1e-16f);
        float4 v0 = reinterpret_cast<const float4*>(ar0 + (size_t)m * HID)[c4];
        float4 v2 = reinterpret_cast<const float4*>(ar2 + (size_t)m * HID)[c4];
        o = make_float4(v0.x * inv0 + v2.x * inv2, v0.y * inv0 + v2.y * inv2,
                        v0.z * inv0 + v2.z * inv2, v0.w * inv0 + v2.w * inv2);
    }
    o.x = __uint_as_float(f2tf32(gelu_exact(o.x)));
    o.y = __uint_as_float(f2tf32(gelu_exact(o.y)));
    o.z = __uint_as_float(f2tf32(gelu_exact(o.z)));
    o.w = __uint_as_float(f2tf32(gelu_exact(o.w)));
    reinterpret_cast<float4*>(agg + (size_t)n * HID)[c4] = o;
}

// ---------------------------------------------------------------------------
// Host orchestration
// ---------------------------------------------------------------------------
extern "C" void kernel_launch(void* const* d_in, const int* in_sizes, int n_in,
                              void* d_out, int out_size)
{
    const float* x0   = (const float*)d_in[0];
    const float* x1   = (const float*)d_in[1];
    const int* srcp[3] = {(const int*)d_in[2], (const int*)d_in[4], (const int*)d_in[6]};
    const int* dstp[3] = {(const int*)d_in[3], (const int*)d_in[5], (const int*)d_in[7]};
    const int  Ecnt[3] = {in_sizes[2], in_sizes[4], in_sizes[6]};
    const float* W_in = (const float*)d_in[8];
    const float* b_in = (const float*)d_in[9];
    const float* Wk   = (const float*)d_in[10];
    const float* bk   = (const float*)d_in[11];
    const float* Wq   = (const float*)d_in[12];
    const float* bq   = (const float*)d_in[13];
    const float* Wv   = (const float*)d_in[14];
    const float* bv   = (const float*)d_in[15];
    const float* Wa   = (const float*)d_in[16];
    const float* ba   = (const float*)d_in[17];
    const float* skip = (const float*)d_in[18];
    const float* a_rel = (const float*)d_in[19];
    const float* m_rel = (const float*)d_in[20];
    const float* p_rel = (const float*)d_in[21];

    float* out = (float*)d_out;
    const int OW = HID * (NL + 1);       // 384
    float* y0 = out;
    float* y1 = out + (size_t)N0 * OW;

    float *q0, *q1, *agg, *aggr, *wcat0, *wcat1, *bcat0, *bcat1, *win, *wa;
    __half *kv0, *kv1;
    cudaGetSymbolAddress((void**)&q0,    g_q0);
    cudaGetSymbolAddress((void**)&q1,    g_q1);
    cudaGetSymbolAddress((void**)&kv0,   g_kv0);
    cudaGetSymbolAddress((void**)&kv1,   g_kv1);
    cudaGetSymbolAddress((void**)&agg,   g_agg);
    cudaGetSymbolAddress((void**)&aggr,  g_aggr);
    cudaGetSymbolAddress((void**)&wcat0, g_wcat0);
    cudaGetSymbolAddress((void**)&wcat1, g_wcat1);
    cudaGetSymbolAddress((void**)&bcat0, g_bcat0);
    cudaGetSymbolAddress((void**)&bcat1, g_bcat1);
    cudaGetSymbolAddress((void**)&win,   g_win);
    cudaGetSymbolAddress((void**)&wa,    g_wa);
    float* ssum = aggr + AGGR_FLOATS;

    cudaFuncSetAttribute(gemm_tc<0,1,1>, cudaFuncAttributeMaxDynamicSharedMemorySize, GEMM_SMEM);
    cudaFuncSetAttribute(gemm_tc<1,1,0>, cudaFuncAttributeMaxDynamicSharedMemorySize, GEMM_SMEM);
    cudaFuncSetAttribute(gemm_tc<2,0,0>, cudaFuncAttributeMaxDynamicSharedMemorySize, GEMM_SMEM);

    // ---- ALL weight prep in one launch (22 sections)
    {
        WPrepN P;
        P.s[0] = {W_in,             b_in, nullptr, win,             nullptr, HID};
        P.s[1] = {W_in + HID * HID, b_in, nullptr, win + HID * HID, nullptr, HID};
        for (int l = 0; l < NL; l++) {
            float* wc0 = wcat0 + (size_t)l * HID * LD0;
            float* wc1 = wcat1 + (size_t)l * HID * LD1;
            float* bc0 = bcat0 + (size_t)l * LD0;
            float* bc1 = bcat1 + (size_t)l * LD1;
            float* wal = wa + (size_t)l * 2 * HID * HID;
            const float* WkL0 = Wk + (size_t)(l * 2 + 0) * HID * HID;
            const float* WkL1 = Wk + (size_t)(l * 2 + 1) * HID * HID;
            const float* WvL0 = Wv + (size_t)(l * 2 + 0) * HID * HID;
            const float* WvL1 = Wv + (size_t)(l * 2 + 1) * HID * HID;
            const float* ar0 = a_rel + (size_t)(l * 3 + 0) * NH * HD * HD;
            const float* ar1 = a_rel + (size_t)(l * 3 + 1) * NH * HD * HD;
            const float* ar2 = a_rel + (size_t)(l * 3 + 2) * NH * HD * HD;
            const float* mr0 = m_rel + (size_t)(l * 3 + 0) * NH * HD * HD;
            const float* mr1 = m_rel + (size_t)(l * 3 + 1) * NH * HD * HD;
            const float* mr2 = m_rel + (size_t)(l * 3 + 2) * NH * HD * HD;
            int o = 2 + l * 10;
            P.s[o + 0] = {Wq + (size_t)(l*2+0)*HID*HID, bq + (l*2+0)*HID, nullptr, wc0,       bc0,       LD0};
            P.s[o + 1] = {WkL0, bk + (l*2+0)*HID, ar0, wc0 + 128, bc0 + 128, LD0};
            P.s[o + 2] = {WvL0, bv + (l*2+0)*HID, mr0, wc0 + 256, bc0 + 256, LD0};
            P.s[o + 3] = {Wq + (size_t)(l*2+1)*HID*HID, bq + (l*2+1)*HID, nullptr, wc1,       bc1,       LD1};
            P.s[o + 4] = {WkL1, bk + (l*2+1)*HID, ar1, wc1 + 128, bc1 + 128, LD1};
            P.s[o + 5] = {WvL1, bv + (l*2+1)*HID, mr1, wc1 + 256, bc1 + 256, LD1};
            P.s[o + 6] = {WkL1, bk + (l*2+1)*HID, ar2, wc1 + 384, bc1 + 384, LD1};
            P.s[o + 7] = {WvL1, bv + (l*2+1)*HID, mr2, wc1 + 512, bc1 + 512, LD1};
            P.s[o + 8] = {Wa + (size_t)(l*2+0)*HID*HID, nullptr, nullptr, wal,             nullptr, HID};
            P.s[o + 9] = {Wa + (size_t)(l*2+1)*HID*HID, nullptr, nullptr, wal + HID * HID, nullptr, HID};
        }
        prep_w_k<<<dim3(HID + 1, 22), HID>>>(P);
    }

    // ---- input projection (both types, one launch)
    {
        GemmPair P;
        P.nb0 = NB0;
        P.s[0] = {x0, HID, win,             HID, b_in,       y0, OW, nullptr, 0, N0, 1, nullptr, 0, nullptr};
        P.s[1] = {x1, HID, win + HID * HID, HID, b_in + HID, y1, OW, nullptr, 0, N1, 1, nullptr, 0, nullptr};
        gemm_tc<1,1,0><<<dim3(NB0 + NB1, 1), 512, GEMM_SMEM>>>(P);
    }

    for (int l = 0; l < NL; l++) {
        const float* h0 = y0 + l * HID;  // lda = OW
        const float* h1 = y1 + l * HID;
        const float* wc0 = wcat0 + (size_t)l * HID * LD0;
        const float* wc1 = wcat1 + (size_t)l * HID * LD1;
        const float* bc0 = bcat0 + (size_t)l * LD0;
        const float* bc1 = bcat1 + (size_t)l * LD1;
        const float* wal = wa + (size_t)l * 2 * HID * HID;

        // ---- fused qkv projections: Q -> fp32, K/V -> fp16
        {
            GemmPair P;
            P.nb0 = NB0;
            P.s[0] = {h0, OW, wc0, LD0, bc0, q0, HID, kv0, KV0, N0, LD0 / GBN, nullptr, 0, nullptr};
            P.s[1] = {h1, OW, wc1, LD1, bc1, q1, HID, kv1, KV1, N1, LD1 / GBN, nullptr, 0, nullptr};
            gemm_tc<0,1,1><<<dim3(NB0 + NB1, LD1 / GBN), 512, GEMM_SMEM>>>(P);
        }

        // one memset covers aggr + ssum (contiguous)
        cudaMemsetAsync(aggr, 0, (AGGR_FLOATS + SSUM_FLOATS) * sizeof(float), 0);

        // ---- single-pass fused edge stage (q fp32, k/v fp16)
        Edge3 EP;
        float* aggr_tab[3] = {aggr,
                              aggr + (size_t)N1 * HID,
                              aggr + (size_t)(N1 + N0) * HID};
        // r0: src type0, dst type1
        EP.r[0] = {srcp[0], dstp[0], q1, HID, kv0, kv0 + 128, KV0,
                   p_rel + (size_t)(l * 3 + 0) * NH, ssum, aggr_tab[0]};
        // r1: src type1, dst type0
        EP.r[1] = {srcp[1], dstp[1], q0, HID, kv1, kv1 + 128, KV1,
                   p_rel + (size_t)(l * 3 + 1) * NH, ssum + (size_t)N0 * NH, aggr_tab[1]};
        // r2: src type1, dst type1
        EP.r[2] = {srcp[2], dstp[2], q1, HID, kv1 + 256, kv1 + 384, KV1,
                   p_rel + (size_t)(l * 3 + 2) * NH, ssum + (size_t)2 * N0 * NH, aggr_tab[2]};
        EP.off1 = Ecnt[0];
        EP.off2 = Ecnt[0] + Ecnt[1];
        EP.total = Ecnt[0] + Ecnt[1] + Ecnt[2];
        int eBlocks = (EP.total + 7) / 8;
        edge_fused_k<<<eBlocks, 256>>>(EP);

        // ---- combine + gelu + round
        int cThreads = (N0 + N1) * (HID / 4);
        combine_k<<<(cThreads + 255) / 256, 256>>>(aggr, ssum, agg);

        // ---- output projection + skip blend (both types, one launch)
        {
            GemmPair P;
            P.nb0 = NB0;
            P.s[0] = {agg, HID, wal, HID, ba + (l * 2 + 0) * HID,
                      y0 + (l + 1) * HID, OW, nullptr, 0, N0, 1, h0, OW, skip + l * 2 + 0};
            P.s[1] = {agg + (size_t)N0 * HID, HID, wal + HID * HID, HID,
                      ba + (l * 2 + 1) * HID,
                      y1 + (l + 1) * HID, OW, nullptr, 0, N1, 1, h1, OW, skip + l * 2 + 1};
            gemm_tc<2,0,0><<<dim3(NB0 + NB1, 1), 512, GEMM_SMEM>>>(P);
        }
    }
}

// round 14
// speedup vs baseline: 1.5368x; 1.0140x over previous
#include <cuda_runtime.h>
#include <cuda_fp16.h>
#include <math.h>
#include <stdint.h>

// ---------------------------------------------------------------------------
// Problem constants
// ---------------------------------------------------------------------------
#define N0 100000
#define N1 50000
#define HID 128
#define NH 4
#define HD 32
#define NL 2

#define LD0 384   // type0 weights: Q | K_r0 | V_r0
#define LD1 640   // type1 weights: Q | K_r1 | V_r1 | K_r2 | V_r2
#define KV0 256   // halves per type0 kv row (k@0, v@128)
#define KV1 512   // halves per type1 kv row (k1@0, v1@128, k2@256, v2@384)

#define NB0 ((N0 + 127) / 128)
#define NB1 ((N1 + 127) / 128)

#define AGGR_FLOATS ((size_t)(N0 + 2 * N1) * HID)
#define SSUM_FLOATS ((size_t)3 * N0 * NH)

// ---------------------------------------------------------------------------
// Static device scratch
// ---------------------------------------------------------------------------
__device__ __half g_q0[(size_t)N0 * HID];
__device__ __half g_q1[(size_t)N1 * HID];
__device__ __half g_kv0[(size_t)N0 * KV0];
__device__ __half g_kv1[(size_t)N1 * KV1];
__device__ float  g_agg[(size_t)(N0 + N1) * HID];
__device__ float  g_aggr[AGGR_FLOATS + SSUM_FLOATS];
__device__ float  g_wcat0[NL * HID * LD0];
__device__ float  g_wcat1[NL * HID * LD1];
__device__ float  g_bcat0[NL * LD0];
__device__ float  g_bcat1[NL * LD1];
__device__ float  g_win[2 * HID * HID];
__device__ float  g_wa[NL * 2 * HID * HID];

// ---------------------------------------------------------------------------
// Helpers
// ---------------------------------------------------------------------------
__device__ __forceinline__ float gelu_exact(float x) {
    return 0.5f * x * (1.0f + erff(x * 0.7071067811865476f));
}
__device__ __forceinline__ unsigned f2tf32(float f) {
    unsigned u;
    asm("cvt.rna.tf32.f32 %0, %1;" : "=r"(u) : "f"(f));
    return u;
}
__device__ __forceinline__ void mma_tf32(float* c, const unsigned* a, const unsigned* b) {
    asm("mma.sync.aligned.m16n8k8.row.col.f32.tf32.tf32.f32 "
        "{%0,%1,%2,%3}, {%4,%5,%6,%7}, {%8,%9}, {%0,%1,%2,%3};"
        : "+f"(c[0]), "+f"(c[1]), "+f"(c[2]), "+f"(c[3])
        : "r"(a[0]), "r"(a[1]), "r"(a[2]), "r"(a[3]), "r"(b[0]), "r"(b[1]));
}
__device__ __forceinline__ void cpa16(float* dst, const float* src) {
    unsigned d = (unsigned)__cvta_generic_to_shared(dst);
    asm volatile("cp.async.cg.shared.global [%0], [%1], 16;" :: "r"(d), "l"(src));
}
__device__ __forceinline__ void cp_commit() { asm volatile("cp.async.commit_group;"); }
template <int N>
__device__ __forceinline__ void cp_wait() {
    asm volatile("cp.async.wait_group %0;" :: "n"(N));
}

// ---------------------------------------------------------------------------
// Paired TF32 TC GEMM. OUTH=1: all tiles write fp16 — blockIdx.y==0 into Cq
// (Q section, ld HID halves), y>=1 into Ckv at column (col-128).
//   EPI: 0 none, 1 relu, 2 skip-blend with hprev   CVT_A: round A at frag load
// ---------------------------------------------------------------------------
#define GBM 128
#define GBN 128
#define AS_LD 20
#define BS_LD 136
#define A_STG (128 * AS_LD)
#define B_STG (16 * BS_LD)
#define GEMM_SMEM (3 * (A_STG + B_STG) * 4)

struct GemmSide {
    const float* A; int lda;
    const float* B; int ldb;
    const float* bias;
    float* C; int ldc;
    __half* Cq;
    __half* Ckv; int ldkv;
    int M; int nby;
    const float* hprev; int ldh;
    const float* skipPtr;
};
struct GemmPair { GemmSide s[2]; int nb0; };

template <int EPI, int CVT_A, int OUTH>
__global__ __launch_bounds__(512, 2) void gemm_tc(GemmPair P)
{
    extern __shared__ float smemf[];
    float* AsBase = smemf;
    float* BsBase = smemf + 3 * A_STG;

    const int side = (blockIdx.x >= (unsigned)P.nb0);
    const GemmSide S = P.s[side];
    const int bx = side ? (blockIdx.x - P.nb0) : blockIdx.x;
    if ((int)blockIdx.y >= S.nby) return;

    const int tid  = threadIdx.x;
    const int wid  = tid >> 5;
    const int lane = tid & 31;
    const int row0 = bx * GBM;
    const int col0 = blockIdx.y * GBN;
    const int wm0  = (wid >> 2) * 32;
    const int wn0  = (wid & 3) * 32;
    const int g    = lane >> 2;
    const int tig  = lane & 3;

    const int rA = tid >> 2, kcA = (tid & 3) << 2;
    const int kB = tid >> 5, ncB = (tid & 31) << 2;
    int gArow = row0 + rA; if (gArow >= S.M) gArow = S.M - 1;
    const float* gA = S.A + (size_t)gArow * S.lda + kcA;
    const float* gB = S.B + (size_t)kB * S.ldb + col0 + ncB;
    const int ldb = S.ldb;

    auto stage_load = [&](int s, int k0) {
        cpa16(AsBase + s * A_STG + rA * AS_LD + kcA, gA + k0);
        cpa16(BsBase + s * B_STG + kB * BS_LD + ncB, gB + (size_t)k0 * ldb);
    };

    stage_load(0, 0);  cp_commit();
    stage_load(1, 16); cp_commit();

    float acc[2][4][4];
#pragma unroll
    for (int i = 0; i < 2; i++)
#pragma unroll
        for (int j = 0; j < 4; j++)
#pragma unroll
            for (int q = 0; q < 4; q++) acc[i][j][q] = 0.f;

#pragma unroll
    for (int kt = 0; kt < 8; kt++) {
        cp_wait<1>();
        __syncthreads();
        if (kt + 2 < 8) stage_load((kt + 2) % 3, (kt + 2) * 16);
        cp_commit();

        const float* Ast = AsBase + (kt % 3) * A_STG;
        const float* Bst = BsBase + (kt % 3) * B_STG;
#pragma unroll
        for (int k8 = 0; k8 < 2; k8++) {
            const int kk = k8 * 8;
            unsigned aR[2][4], bR[4][2];
#pragma unroll
            for (int mt = 0; mt < 2; mt++) {
                int m = wm0 + mt * 16 + g;
                float a0 = Ast[(size_t)m * AS_LD + kk + tig];
                float a1 = Ast[(size_t)(m + 8) * AS_LD + kk + tig];
                float a2 = Ast[(size_t)m * AS_LD + kk + tig + 4];
                float a3 = Ast[(size_t)(m + 8) * AS_LD + kk + tig + 4];
                if (CVT_A) {
                    aR[mt][0] = f2tf32(a0); aR[mt][1] = f2tf32(a1);
                    aR[mt][2] = f2tf32(a2); aR[mt][3] = f2tf32(a3);
                } else {
                    aR[mt][0] = __float_as_uint(a0); aR[mt][1] = __float_as_uint(a1);
                    aR[mt][2] = __float_as_uint(a2); aR[mt][3] = __float_as_uint(a3);
                }
            }
#pragma unroll
            for (int nt = 0; nt < 4; nt++) {
                int n = wn0 + nt * 8 + g;
                bR[nt][0] = __float_as_uint(Bst[(size_t)(kk + tig) * BS_LD + n]);
                bR[nt][1] = __float_as_uint(Bst[(size_t)(kk + tig + 4) * BS_LD + n]);
            }
#pragma unroll
            for (int mt = 0; mt < 2; mt++)
#pragma unroll
                for (int nt = 0; nt < 4; nt++)
                    mma_tf32(acc[mt][nt], aR[mt], bR[nt]);
        }
    }

    float sgate = 0.f;
    if (EPI == 2) sgate = 1.f / (1.f + expf(-(*S.skipPtr)));

#pragma unroll
    for (int mt = 0; mt < 2; mt++) {
#pragma unroll
        for (int rr = 0; rr < 2; rr++) {
            int grow = row0 + wm0 + mt * 16 + g + rr * 8;
            if (grow >= S.M) continue;
#pragma unroll
            for (int nt = 0; nt < 4; nt++) {
                int col = col0 + wn0 + nt * 8 + 2 * tig;
                float v0 = acc[mt][nt][rr * 2 + 0] + S.bias[col];
                float v1 = acc[mt][nt][rr * 2 + 1] + S.bias[col + 1];
                if (EPI == 1) { v0 = fmaxf(v0, 0.f); v1 = fmaxf(v1, 0.f); }
                if (EPI == 2) {
                    const float* hp = S.hprev + (size_t)grow * S.ldh + col;
                    v0 = sgate * v0 + (1.f - sgate) * hp[0];
                    v1 = sgate * v1 + (1.f - sgate) * hp[1];
                }
                if (OUTH == 1) {
                    __half2 hv = __floats2half2_rn(v0, v1);
                    if (blockIdx.y == 0)
                        *reinterpret_cast<__half2*>(
                            S.Cq + (size_t)grow * HID + col) = hv;
                    else
                        *reinterpret_cast<__half2*>(
                            S.Ckv + (size_t)grow * S.ldkv + (col - 128)) = hv;
                } else {
                    *reinterpret_cast<float2*>(S.C + (size_t)grow * S.ldc + col) =
                        make_float2(v0, v1);
                }
            }
        }
    }
}

// ---------------------------------------------------------------------------
// Weight prep: 22 sections in one launch. A==nullptr -> tf32-rounded copy.
// ---------------------------------------------------------------------------
struct WPrepSec {
    const float* W; const float* b; const float* A;
    float* Wd; float* bd; int ld;
};
struct WPrepN { WPrepSec s[22]; };

__global__ void prep_w_k(WPrepN P)
{
    WPrepSec p = P.s[blockIdx.y];
    int col = threadIdx.x;
    int i = blockIdx.x;
    if (p.A == nullptr) {
        if (i < HID)
            p.Wd[(size_t)i * p.ld + col] =
                __uint_as_float(f2tf32(p.W[(size_t)i * HID + col]));
        else if (p.bd) p.bd[col] = p.b[col];
        return;
    }
    int h = col >> 5, e = col & 31;
    const float* Ah = p.A + h * HD * HD;
    if (i < HID) {
        const float* wrow = p.W + (size_t)i * HID + h * HD;
        float acc = 0.f;
#pragma unroll
        for (int d = 0; d < HD; d++) acc = fmaf(wrow[d], Ah[d * HD + e], acc);
        p.Wd[(size_t)i * p.ld + col] = __uint_as_float(f2tf32(acc));
    } else if (p.bd) {
        const float* brow = p.b + h * HD;
        float acc = 0.f;
#pragma unroll
        for (int d = 0; d < HD; d++) acc = fmaf(brow[d], Ah[d * HD + e], acc);
        p.bd[col] = acc;
    }
}

// ---------------------------------------------------------------------------
// Single-pass fused edge kernel (warp per edge). q, k, v all fp16.
// ---------------------------------------------------------------------------
struct EdgeRel {
    const int* src; const int* dst;
    const __half* q;
    const __half* k; const __half* v; int ldkv;
    const float* prel;
    float* ssum; float* aggr;
};
struct Edge3 { EdgeRel r[3]; int off1, off2, total; };

__global__ void edge_fused_k(Edge3 P)
{
    int w = blockIdx.x * (blockDim.x >> 5) + (threadIdx.x >> 5);
    if (w >= P.total) return;
    int lane = threadIdx.x & 31;
    int ri = (w >= P.off1) + (w >= P.off2);
    int base = ri == 0 ? 0 : (ri == 1 ? P.off1 : P.off2);
    EdgeRel R = P.r[ri];
    int e = w - base;
    int s = __ldg(&R.src[e]), d = __ldg(&R.dst[e]);
    uint2 qraw = *reinterpret_cast<const uint2*>(R.q + (size_t)d * HID + lane * 4);
    float2 q0 = __half22float2(*reinterpret_cast<__half2*>(&qraw.x));
    float2 q1 = __half22float2(*reinterpret_cast<__half2*>(&qraw.y));
    uint2 kraw = *reinterpret_cast<const uint2*>(R.k + (size_t)s * R.ldkv + lane * 4);
    float2 k0 = __half22float2(*reinterpret_cast<__half2*>(&kraw.x));
    float2 k1 = __half22float2(*reinterpret_cast<__half2*>(&kraw.y));
    float acc = q0.x * k0.x + q0.y * k0.y + q1.x * k1.x + q1.y * k1.y;
    acc += __shfl_xor_sync(0xffffffffu, acc, 1);
    acc += __shfl_xor_sync(0xffffffffu, acc, 2);
    acc += __shfl_xor_sync(0xffffffffu, acc, 4);
    int h = lane >> 3;
    float a = acc * __ldg(&R.prel[h]) * 0.17677669529663689f; // 1/sqrt(32)
    float ex = expf(a);
    uint2 vraw = *reinterpret_cast<const uint2*>(R.v + (size_t)s * R.ldkv + lane * 4);
    float2 v0 = __half22float2(*reinterpret_cast<__half2*>(&vraw.x));
    float2 v1 = __half22float2(*reinterpret_cast<__half2*>(&vraw.y));
    float* p = R.aggr + (size_t)d * HID + lane * 4;
    asm volatile("red.global.add.v4.f32 [%0], {%1,%2,%3,%4};"
                 :: "l"(p), "f"(v0.x * ex), "f"(v0.y * ex),
                    "f"(v1.x * ex), "f"(v1.y * ex)
                 : "memory");
    if ((lane & 7) == 0)
        atomicAdd(&R.ssum[(size_t)d * NH + h], ex);
}

// ---------------------------------------------------------------------------
// Combiner: normalize per-relation aggregates, sum, gelu, tf32 round.
// ---------------------------------------------------------------------------
__global__ void combine_k(const float* __restrict__ aggr,
                          const float* __restrict__ ssum,
                          float* __restrict__ agg)
{
    int idx = blockIdx.x * blockDim.x + threadIdx.x;
    int total = (N0 + N1) * (HID / 4);
    if (idx >= total) return;
    int n = idx >> 5;
    int c4 = idx & 31;
    int h = c4 >> 3;
    float4 o;
    if (n < N0) {
        const float* ar = aggr + (size_t)N1 * HID;
        float inv = 1.f / (ssum[(size_t)N0 * NH * 1 + (size_t)n * NH + h] + 1e-16f);
        float4 v = reinterpret_cast<const float4*>(ar + (size_t)n * HID)[c4];
        o = make_float4(v.x * inv, v.y * inv, v.z * inv, v.w * inv);
    } else {
        int m = n - N0;
        const float* ar0 = aggr;
        const float* ar2 = aggr + (size_t)(N1 + N0) * HID;
        float inv0 = 1.f / (ssum[(size_t)m * NH + h] + 1e-16f);
        float inv2 = 1.f / (ssum[(size_t)N0 * NH * 2 + (size_t)m * NH + h] + 1e-16f);
        float4 v0 = reinterpret_cast<const float4*>(ar0 + (size_t)m * HID)[c4];
        float4 v2 = reinterpret_cast<const float4*>(ar2 + (size_t)m * HID)[c4];
        o = make_float4(v0.x * inv0 + v2.x * inv2, v0.y * inv0 + v2.y * inv2,
                        v0.z * inv0 + v2.z * inv2, v0.w * inv0 + v2.w * inv2);
    }
    o.x = __uint_as_float(f2tf32(gelu_exact(o.x)));
    o.y = __uint_as_float(f2tf32(gelu_exact(o.y)));
    o.z = __uint_as_float(f2tf32(gelu_exact(o.z)));
    o.w = __uint_as_float(f2tf32(gelu_exact(o.w)));
    reinterpret_cast<float4*>(agg + (size_t)n * HID)[c4] = o;
}

// ---------------------------------------------------------------------------
// Host orchestration
// ---------------------------------------------------------------------------
extern "C" void kernel_launch(void* const* d_in, const int* in_sizes, int n_in,
                              void* d_out, int out_size)
{
    const float* x0   = (const float*)d_in[0];
    const float* x1   = (const float*)d_in[1];
    const int* srcp[3] = {(const int*)d_in[2], (const int*)d_in[4], (const int*)d_in[6]};
    const int* dstp[3] = {(const int*)d_in[3], (const int*)d_in[5], (const int*)d_in[7]};
    const int  Ecnt[3] = {in_sizes[2], in_sizes[4], in_sizes[6]};
    const float* W_in = (const float*)d_in[8];
    const float* b_in = (const float*)d_in[9];
    const float* Wk   = (const float*)d_in[10];
    const float* bk   = (const float*)d_in[11];
    const float* Wq   = (const float*)d_in[12];
    const float* bq   = (const float*)d_in[13];
    const float* Wv   = (const float*)d_in[14];
    const float* bv   = (const float*)d_in[15];
    const float* Wa   = (const float*)d_in[16];
    const float* ba   = (const float*)d_in[17];
    const float* skip = (const float*)d_in[18];
    const float* a_rel = (const float*)d_in[19];
    const float* m_rel = (const float*)d_in[20];
    const float* p_rel = (const float*)d_in[21];

    float* out = (float*)d_out;
    const int OW = HID * (NL + 1);       // 384
    float* y0 = out;
    float* y1 = out + (size_t)N0 * OW;

    float *agg, *aggr, *wcat0, *wcat1, *bcat0, *bcat1, *win, *wa;
    __half *q0, *q1, *kv0, *kv1;
    cudaGetSymbolAddress((void**)&q0,    g_q0);
    cudaGetSymbolAddress((void**)&q1,    g_q1);
    cudaGetSymbolAddress((void**)&kv0,   g_kv0);
    cudaGetSymbolAddress((void**)&kv1,   g_kv1);
    cudaGetSymbolAddress((void**)&agg,   g_agg);
    cudaGetSymbolAddress((void**)&aggr,  g_aggr);
    cudaGetSymbolAddress((void**)&wcat0, g_wcat0);
    cudaGetSymbolAddress((void**)&wcat1, g_wcat1);
    cudaGetSymbolAddress((void**)&bcat0, g_bcat0);
    cudaGetSymbolAddress((void**)&bcat1, g_bcat1);
    cudaGetSymbolAddress((void**)&win,   g_win);
    cudaGetSymbolAddress((void**)&wa,    g_wa);
    float* ssum = aggr + AGGR_FLOATS;

    cudaFuncSetAttribute(gemm_tc<0,1,1>, cudaFuncAttributeMaxDynamicSharedMemorySize, GEMM_SMEM);
    cudaFuncSetAttribute(gemm_tc<1,1,0>, cudaFuncAttributeMaxDynamicSharedMemorySize, GEMM_SMEM);
    cudaFuncSetAttribute(gemm_tc<2,0,0>, cudaFuncAttributeMaxDynamicSharedMemorySize, GEMM_SMEM);

    // ---- ALL weight prep in one launch (22 sections)
    {
        WPrepN P;
        P.s[0] = {W_in,             b_in, nullptr, win,             nullptr, HID};
        P.s[1] = {W_in + HID * HID, b_in, nullptr, win + HID * HID, nullptr, HID};
        for (int l = 0; l < NL; l++) {
            float* wc0 = wcat0 + (size_t)l * HID * LD0;
            float* wc1 = wcat1 + (size_t)l * HID * LD1;
            float* bc0 = bcat0 + (size_t)l * LD0;
            float* bc1 = bcat1 + (size_t)l * LD1;
            float* wal = wa + (size_t)l * 2 * HID * HID;
            const float* WkL0 = Wk + (size_t)(l * 2 + 0) * HID * HID;
            const float* WkL1 = Wk + (size_t)(l * 2 + 1) * HID * HID;
            const float* WvL0 = Wv + (size_t)(l * 2 + 0) * HID * HID;
            const float* WvL1 = Wv + (size_t)(l * 2 + 1) * HID * HID;
            const float* ar0 = a_rel + (size_t)(l * 3 + 0) * NH * HD * HD;
            const float* ar1 = a_rel + (size_t)(l * 3 + 1) * NH * HD * HD;
            const float* ar2 = a_rel + (size_t)(l * 3 + 2) * NH * HD * HD;
            const float* mr0 = m_rel + (size_t)(l * 3 + 0) * NH * HD * HD;
            const float* mr1 = m_rel + (size_t)(l * 3 + 1) * NH * HD * HD;
            const float* mr2 = m_rel + (size_t)(l * 3 + 2) * NH * HD * HD;
            int o = 2 + l * 10;
            P.s[o + 0] = {Wq + (size_t)(l*2+0)*HID*HID, bq + (l*2+0)*HID, nullptr, wc0,       bc0,       LD0};
            P.s[o + 1] = {WkL0, bk + (l*2+0)*HID, ar0, wc0 + 128, bc0 + 128, LD0};
            P.s[o + 2] = {WvL0, bv + (l*2+0)*HID, mr0, wc0 + 256, bc0 + 256, LD0};
            P.s[o + 3] = {Wq + (size_t)(l*2+1)*HID*HID, bq + (l*2+1)*HID, nullptr, wc1,       bc1,       LD1};
            P.s[o + 4] = {WkL1, bk + (l*2+1)*HID, ar1, wc1 + 128, bc1 + 128, LD1};
            P.s[o + 5] = {WvL1, bv + (l*2+1)*HID, mr1, wc1 + 256, bc1 + 256, LD1};
            P.s[o + 6] = {WkL1, bk + (l*2+1)*HID, ar2, wc1 + 384, bc1 + 384, LD1};
            P.s[o + 7] = {WvL1, bv + (l*2+1)*HID, mr2, wc1 + 512, bc1 + 512, LD1};
            P.s[o + 8] = {Wa + (size_t)(l*2+0)*HID*HID, nullptr, nullptr, wal,             nullptr, HID};
            P.s[o + 9] = {Wa + (size_t)(l*2+1)*HID*HID, nullptr, nullptr, wal + HID * HID, nullptr, HID};
        }
        prep_w_k<<<dim3(HID + 1, 22), HID>>>(P);
    }

    // ---- input projection (both types, one launch)
    {
        GemmPair P;
        P.nb0 = NB0;
        P.s[0] = {x0, HID, win,             HID, b_in,       y0, OW, nullptr, nullptr, 0, N0, 1, nullptr, 0, nullptr};
        P.s[1] = {x1, HID, win + HID * HID, HID, b_in + HID, y1, OW, nullptr, nullptr, 0, N1, 1, nullptr, 0, nullptr};
        gemm_tc<1,1,0><<<dim3(NB0 + NB1, 1), 512, GEMM_SMEM>>>(P);
    }

    for (int l = 0; l < NL; l++) {
        const float* h0 = y0 + l * HID;  // lda = OW
        const float* h1 = y1 + l * HID;
        const float* wc0 = wcat0 + (size_t)l * HID * LD0;
        const float* wc1 = wcat1 + (size_t)l * HID * LD1;
        const float* bc0 = bcat0 + (size_t)l * LD0;
        const float* bc1 = bcat1 + (size_t)l * LD1;
        const float* wal = wa + (size_t)l * 2 * HID * HID;

        // ---- fused qkv projections: all sections -> fp16
        {
            GemmPair P;
            P.nb0 = NB0;
            P.s[0] = {h0, OW, wc0, LD0, bc0, nullptr, 0, q0, kv0, KV0, N0, LD0 / GBN, nullptr, 0, nullptr};
            P.s[1] = {h1, OW, wc1, LD1, bc1, nullptr, 0, q1, kv1, KV1, N1, LD1 / GBN, nullptr, 0, nullptr};
            gemm_tc<0,1,1><<<dim3(NB0 + NB1, LD1 / GBN), 512, GEMM_SMEM>>>(P);
        }

        // one memset covers aggr + ssum (contiguous)
        cudaMemsetAsync(aggr, 0, (AGGR_FLOATS + SSUM_FLOATS) * sizeof(float), 0);

        // ---- single-pass fused edge stage (all fp16 gathers)
        Edge3 EP;
        float* aggr_tab[3] = {aggr,
                              aggr + (size_t)N1 * HID,
                              aggr + (size_t)(N1 + N0) * HID};
        EP.r[0] = {srcp[0], dstp[0], q1, kv0, kv0 + 128, KV0,
                   p_rel + (size_t)(l * 3 + 0) * NH, ssum, aggr_tab[0]};
        EP.r[1] = {srcp[1], dstp[1], q0, kv1, kv1 + 128, KV1,
                   p_rel + (size_t)(l * 3 + 1) * NH, ssum + (size_t)N0 * NH, aggr_tab[1]};
        EP.r[2] = {srcp[2], dstp[2], q1, kv1 + 256, kv1 + 384, KV1,
                   p_rel + (size_t)(l * 3 + 2) * NH, ssum + (size_t)2 * N0 * NH, aggr_tab[2]};
        EP.off1 = Ecnt[0];
        EP.off2 = Ecnt[0] + Ecnt[1];
        EP.total = Ecnt[0] + Ecnt[1] + Ecnt[2];
        int eBlocks = (EP.total + 7) / 8;
        edge_fused_k<<<eBlocks, 256>>>(EP);

        // ---- combine + gelu + round
        int cThreads = (N0 + N1) * (HID / 4);
        combine_k<<<(cThreads + 255) / 256, 256>>>(aggr, ssum, agg);

        // ---- output projection + skip blend (both types, one launch)
        {
            GemmPair P;
            P.nb0 = NB0;
            P.s[0] = {agg, HID, wal, HID, ba + (l * 2 + 0) * HID,
                      y0 + (l + 1) * HID, OW, nullptr, nullptr, 0, N0, 1, h0, OW, skip + l * 2 + 0};
            P.s[1] = {agg + (size_t)N0 * HID, HID, wal + HID * HID, HID,
                      ba + (l * 2 + 1) * HID,
                      y1 + (l + 1) * HID, OW, nullptr, nullptr, 0, N1, 1, h1, OW, skip + l * 2 + 1};
            gemm_tc<2,0,0><<<dim3(NB0 + NB1, 1), 512, GEMM_SMEM>>>(P);
        }
    }
}